// round 8
// baseline (speedup 1.0000x reference)
#include <cuda_runtime.h>
#include <cuda_fp16.h>
#include <math.h>
#include <stdint.h>

#define HD    1024
#define NL4   4
#define SEQ   512
#define NRW   64
#define LO    256
#define LDC   512
#define NPAIR (NRW*3)
#define MR    (NRW*LO)
#define NEGV  -1e30f

// ---------------------------------------------------------------------------
// Static device scratch
// ---------------------------------------------------------------------------
__device__ float g_opt_enc[MR*HD];
__device__ int   g_opt_mask[MR];
__device__ float g_doc_enc[NRW*LDC*HD];
__device__ int   g_doc_mask[NRW*LDC];
__device__ float g_logitOpt[NPAIR*LO*LO];
__device__ float g_attnOpt[NPAIR*LO*HD];
__device__ float g_X[MR*7*HD];
__device__ float g_corr[MR*HD];
__device__ float g_option[MR*HD];
__device__ float g_logitD[NRW*LO*LDC];
__device__ float g_kq[NRW*LO*LDC];
__device__ float g_attnD[MR*HD];
__device__ float g_cow[NRW*LO*LO];
__device__ float g_coattn[MR*HD];
__device__ float g_fusion[MR*HD];
__device__ float g_logitS[NRW*LO*LO];
__device__ float g_attn2[MR*HD];
__device__ float g_fusion2[MR*HD];
__device__ float g_rowq[MR];
__device__ float g_rowk[MR];
__device__ float g_rowkd[NRW*LDC];

// ---------------------------------------------------------------------------
// Helpers
// ---------------------------------------------------------------------------
__device__ __forceinline__ int read_fp(const int* __restrict__ p, int n)
{
    return (p[1] == 0) ? p[2*n] : p[n];
}

__device__ __forceinline__ void mma_f16(float* c, const uint32_t* a, const uint32_t* b)
{
    asm volatile(
        "mma.sync.aligned.m16n8k16.row.col.f32.f16.f16.f32 "
        "{%0,%1,%2,%3}, {%4,%5,%6,%7}, {%8,%9}, {%0,%1,%2,%3};"
        : "+f"(c[0]), "+f"(c[1]), "+f"(c[2]), "+f"(c[3])
        : "r"(a[0]), "r"(a[1]), "r"(a[2]), "r"(a[3]), "r"(b[0]), "r"(b[1]));
}

__device__ __forceinline__ uint32_t h2u(float a, float b)
{
    __half2 h = __floats2half2_rn(a, b);
    return *(uint32_t*)&h;
}

// ---------------------------------------------------------------------------
// Build kernels
// ---------------------------------------------------------------------------
__global__ void k_build_opt(const float* __restrict__ ll, const int* __restrict__ am,
                            const int* __restrict__ fpw)
{
    int o = blockIdx.x, n = blockIdx.y, t = threadIdx.x;
    int fp = read_fp(fpw, n);
    int idx = fp + o;
    int valid = (idx >= 0) && (idx < SEQ);
    int idxc = valid ? idx : (SEQ - 1);
    int m = valid && (am[n*SEQ + idxc] > 0);
    const float4* src = (const float4*)(ll + (size_t)(n*SEQ + idxc) * HD);
    float4* dst = (float4*)(g_opt_enc + (size_t)(n*LO + o) * HD);
    float4 v = m ? src[t] : make_float4(0.f,0.f,0.f,0.f);
    dst[t] = v;
    if (t == 0) g_opt_mask[n*LO + o] = m;
}

__global__ void k_build_doc(const float* __restrict__ ll, const int* __restrict__ am,
                            const int* __restrict__ fpw)
{
    int t0 = blockIdx.x, n = blockIdx.y, t = threadIdx.x;
    int fp = read_fp(fpw, n);
    int m = (t0 < fp) && (am[n*SEQ + t0] > 0);
    const float4* src = (const float4*)(ll + (size_t)(n*SEQ + t0) * HD);
    float4* dst = (float4*)(g_doc_enc + (size_t)(n*LDC + t0) * HD);
    float4 v = m ? src[t] : make_float4(0.f,0.f,0.f,0.f);
    dst[t] = v;
    if (t == 0) g_doc_mask[n*LDC + t0] = m;
}

__global__ void k_rowdot(const float* __restrict__ X, const float* __restrict__ w,
                         float* __restrict__ out)
{
    int r = blockIdx.x;
    const float* x = X + (size_t)r * HD;
    float s = 0.f;
    for (int i = threadIdx.x; i < HD; i += 256) s += x[i] * w[i];
    __shared__ float sh[256];
    sh[threadIdx.x] = s; __syncthreads();
    for (int st = 128; st > 0; st >>= 1) {
        if (threadIdx.x < st) sh[threadIdx.x] += sh[threadIdx.x + st];
        __syncthreads();
    }
    if (threadIdx.x == 0) out[r] = sh[0];
}

// ---------------------------------------------------------------------------
// Unified 2xFP16 mma GEMM: C = act(A @ op(B) + ...)
//   A[m,k] k-contig, split hi/lo fp16 (exact to ~22 bits).
//   B: BNT=1 -> B[n,k] k-contig; BNT=0 -> B[k,n] n-contig (transposed in smem).
//   B rounded to a single fp16 plane (error ~2^-12, random sign).
// BM=BN=128, BK=16, 8 warps (2m x 4n), m16n8k16 HMMA, double-buffered.
// EPI: 0=none 1=tanh+bias 2=relu+bias 3=sigmoid-gate+bias 4=trilinear logits
// pairMode: 0=strided batches, 1=NT opt pairs, 2=NN opt pairs
// ---------------------------------------------------------------------------
#define PT    544                  // bytes between k-pair planes' rows
#define PLANE (8*PT)               // 4352 B
#define BUFB  (3*PLANE)            // Ahi, Alo, Bhi

template<int EPI, int BNT>
__global__ __launch_bounds__(256, 1) void k_mma(
    const float* __restrict__ A, const float* __restrict__ Bsrc,
    float* __restrict__ C,
    int M, int N, int K, int ldb,
    long sA, long sB, long sC,
    const float* __restrict__ colScale,
    const float* __restrict__ bias,
    const float* __restrict__ ql, const float* __restrict__ kl,
    const int* __restrict__ mq, const int* __restrict__ mk,
    long sQl, long sKl,
    const float* __restrict__ E1, const float* __restrict__ E2,
    int pairMode)
{
    __shared__ __align__(16) char sm[2*BUFB];   // 26112 B
    const int tid = threadIdx.x;
    const int lane = tid & 31, wid = tid >> 5;
    const int wm = wid & 1, wn = wid >> 1;
    const int g = lane >> 2, t = lane & 3;
    const int bm = blockIdx.y << 7, bn = blockIdx.x << 7;
    const int z = blockIdx.z;

    long offA, offB, offC, offQl = 0, offKl = 0;
    if (pairMode) {
        int n = z / 3, jj = z % 3;
        int b = n / NL4, i = n % NL4;
        int j = jj + (jj >= i ? 1 : 0);
        int mb = b * NL4 + j;
        offA = (pairMode == 1 ? (long)n : (long)z) * M * K;
        offB = (long)mb * LO * HD;
        offC = (long)z * M * N;
        offQl = (long)n * LO; offKl = (long)mb * LO;
    } else {
        offA = z * sA; offB = z * sB; offC = z * sC;
        offQl = z * sQl; offKl = z * sKl;
    }

    float acc[4][4][4];
#pragma unroll
    for (int i = 0; i < 4; i++)
#pragma unroll
        for (int q = 0; q < 4; q++)
#pragma unroll
            for (int c = 0; c < 4; c++) acc[i][q][c] = 0.f;

    // Producer: threads 0..127 -> A rows, 128..255 -> B.
    const int prow = tid & 127;
    const bool isA = tid < 128;
    const float* gsrc;
    if (isA)       gsrc = A + offA + (size_t)(bm + prow) * K;
    else if (BNT)  gsrc = Bsrc + offB + (size_t)(bn + prow) * K;
    else           gsrc = Bsrc + offB + bn;   // NN: row-strided by ldb
    float4 st[4];

    auto fetch = [&](int ch) {
        const int k0 = ch << 4;
        if (isA || BNT) {
            const float* p = gsrc + k0;
#pragma unroll
            for (int q = 0; q < 4; q++) st[q] = *(const float4*)(p + (q << 2));
            if (EPI == 4 && !isA) {      // trilinear: scale B rows by colScale[k]
#pragma unroll
                for (int q = 0; q < 4; q++) {
                    float4 cs = *(const float4*)(colScale + k0 + (q << 2));
                    st[q].x *= cs.x; st[q].y *= cs.y; st[q].z *= cs.z; st[q].w *= cs.w;
                }
            }
        } else {
            const int kk0 = (prow >> 5) * 2, c = (prow & 31) * 4;
            const float* p = gsrc + (size_t)(k0 + kk0) * ldb + c;
            st[0] = *(const float4*)p;
            st[1] = *(const float4*)(p + ldb);
            st[2] = *(const float4*)(p + 8 * ldb);
            st[3] = *(const float4*)(p + 9 * ldb);
        }
    };
    auto store_buf = [&](int buf) {
        char* base = sm + buf * BUFB;
        const float* v = (const float*)st;
        if (isA) {
            char* d = base + prow * 4;
#pragma unroll
            for (int tt = 0; tt < 8; ++tt) {
                float x0 = v[2*tt], x1 = v[2*tt + 1];
                __half2 h = __floats2half2_rn(x0, x1);
                float l0 = x0 - __half2float(__low2half(h));
                float l1 = x1 - __half2float(__high2half(h));
                *(uint32_t*)(d + tt*PT) = *(uint32_t*)&h;
                *(uint32_t*)(d + PLANE + tt*PT) = h2u(l0, l1);
            }
        } else if (BNT) {
            char* d = base + 2*PLANE + prow * 4;
#pragma unroll
            for (int tt = 0; tt < 8; ++tt)
                *(uint32_t*)(d + tt*PT) = h2u(v[2*tt], v[2*tt + 1]);
        } else {
            const int p0 = prow >> 5, c = (prow & 31) * 4;
            char* d = base + 2*PLANE + c * 4;
            uint4 u0, u1;
            u0.x = h2u(v[0], v[4]);  u0.y = h2u(v[1], v[5]);
            u0.z = h2u(v[2], v[6]);  u0.w = h2u(v[3], v[7]);
            u1.x = h2u(v[8], v[12]); u1.y = h2u(v[9], v[13]);
            u1.z = h2u(v[10], v[14]); u1.w = h2u(v[11], v[15]);
            *(uint4*)(d + p0 * PT) = u0;
            *(uint4*)(d + (p0 + 4) * PT) = u1;
        }
    };

    const int T = K >> 4;
    fetch(0);
    store_buf(0);
    __syncthreads();

    for (int ch = 0; ch < T; ++ch) {
        const int buf = ch & 1;
        if (ch + 1 < T) fetch(ch + 1);

        const char* Ah = sm + buf * BUFB;
        const char* Al = Ah + PLANE;
        const char* Bh = Ah + 2 * PLANE;
        const int rA = (wm << 6) + g;
        const int rB = (wn << 5) + g;

        uint32_t ah[4][4], al[4][4], bh[4][2];
#pragma unroll
        for (int i = 0; i < 4; i++) {
            const char* p = Ah + t*PT + (rA + (i << 4)) * 4;
            ah[i][0] = *(const uint32_t*)p;
            ah[i][1] = *(const uint32_t*)(p + 32);
            ah[i][2] = *(const uint32_t*)(p + 4*PT);
            ah[i][3] = *(const uint32_t*)(p + 4*PT + 32);
        }
#pragma unroll
        for (int q = 0; q < 4; q++) {
            const char* p = Bh + t*PT + (rB + (q << 3)) * 4;
            bh[q][0] = *(const uint32_t*)p;
            bh[q][1] = *(const uint32_t*)(p + 4*PT);
        }
#pragma unroll
        for (int i = 0; i < 4; i++)
#pragma unroll
            for (int q = 0; q < 4; q++) mma_f16(acc[i][q], ah[i], bh[q]);
#pragma unroll
        for (int i = 0; i < 4; i++) {
            const char* p = Al + t*PT + (rA + (i << 4)) * 4;
            al[i][0] = *(const uint32_t*)p;
            al[i][1] = *(const uint32_t*)(p + 32);
            al[i][2] = *(const uint32_t*)(p + 4*PT);
            al[i][3] = *(const uint32_t*)(p + 4*PT + 32);
        }
#pragma unroll
        for (int i = 0; i < 4; i++)
#pragma unroll
            for (int q = 0; q < 4; q++) mma_f16(acc[i][q], al[i], bh[q]);

        __syncthreads();
        if (ch + 1 < T) store_buf(buf ^ 1);
        __syncthreads();
    }

    // Epilogue
#pragma unroll
    for (int i = 0; i < 4; i++) {
        int row0 = bm + (wm << 6) + (i << 4) + g;
#pragma unroll
        for (int q = 0; q < 4; q++) {
            int col = bn + (wn << 5) + (q << 3) + (t << 1);
            float b0 = 0.f, b1 = 0.f;
            if (EPI == 1 || EPI == 2 || EPI == 3) { b0 = bias[col]; b1 = bias[col+1]; }
#pragma unroll
            for (int h = 0; h < 2; h++) {
                int row = row0 + h * 8;
                float v0 = acc[i][q][h*2+0] + b0;
                float v1 = acc[i][q][h*2+1] + b1;
                size_t ci = offC + (size_t)row * N + col;
                float2 o;
                if (EPI == 0)      { o.x = v0; o.y = v1; }
                else if (EPI == 1) { o.x = tanhf(v0);      o.y = tanhf(v1); }
                else if (EPI == 2) { o.x = fmaxf(v0, 0.f); o.y = fmaxf(v1, 0.f); }
                else if (EPI == 3) {
                    float g0 = 1.f / (1.f + expf(-v0));
                    float g1 = 1.f / (1.f + expf(-v1));
                    o.x = E1[ci]   * g0 + E2[ci]   * (1.f - g0);
                    o.y = E1[ci+1] * g1 + E2[ci+1] * (1.f - g1);
                } else {
                    float qlv = ql[offQl + row];
                    int qmv = mq[offQl + row];
                    o.x = (qmv && mk[offKl + col])   ? v0 + qlv + kl[offKl + col]   : NEGV;
                    o.y = (qmv && mk[offKl + col+1]) ? v1 + qlv + kl[offKl + col+1] : NEGV;
                }
                *(float2*)(C + ci) = o;
            }
        }
    }
}

// ---------------------------------------------------------------------------
// Softmax kernels
// ---------------------------------------------------------------------------
__global__ void k_row_softmax(float* __restrict__ X, int Cdim,
    const int* __restrict__ mqb, const int* __restrict__ mkb,
    long sX, long sMq, long sMk, int pairMode)
{
    int z = blockIdx.y, row = blockIdx.x;
    long offX, offMq, offMk;
    if (pairMode) {
        int n = z / 3, jj = z % 3;
        int b = n / NL4, i = n % NL4;
        int j = jj + (jj >= i ? 1 : 0);
        int mb = b * NL4 + j;
        offX = (long)z * LO * LO; offMq = (long)n * LO; offMk = (long)mb * LO;
    } else { offX = z * sX; offMq = z * sMq; offMk = z * sMk; }
    float* x = X + offX + (long)row * Cdim;
    const int* mk = mkb + offMk;
    int qm = mqb[offMq + row];
    int tid = threadIdx.x;
    __shared__ float sh[256];
    float mx = -3.4e38f;
    for (int c = tid; c < Cdim; c += 256) mx = fmaxf(mx, x[c]);
    sh[tid] = mx; __syncthreads();
    for (int s = 128; s > 0; s >>= 1) {
        if (tid < s) sh[tid] = fmaxf(sh[tid], sh[tid + s]);
        __syncthreads();
    }
    mx = sh[0]; __syncthreads();
    float sum = 0.f;
    for (int c = tid; c < Cdim; c += 256) sum += expf(x[c] - mx);
    sh[tid] = sum; __syncthreads();
    for (int s = 128; s > 0; s >>= 1) {
        if (tid < s) sh[tid] += sh[tid + s];
        __syncthreads();
    }
    float inv = 1.f / sh[0];
    for (int c = tid; c < Cdim; c += 256) {
        float e = expf(x[c] - mx);
        x[c] = (qm && mk[c]) ? e * inv : 0.f;
    }
}

__global__ void k_col_softmax()
{
    int n = blockIdx.y;
    int t = blockIdx.x * 256 + threadIdx.x;
    const float* x = g_logitD + (size_t)n * LO * LDC;
    float mx = -3.4e38f;
    for (int o = 0; o < LO; o++) mx = fmaxf(mx, x[(size_t)o * LDC + t]);
    float sum = 0.f;
    for (int o = 0; o < LO; o++) sum += expf(x[(size_t)o * LDC + t] - mx);
    float inv = 1.f / sum;
    int km = g_doc_mask[n*LDC + t];
    float* y = g_kq + (size_t)n * LO * LDC;
    for (int o = 0; o < LO; o++) {
        float e = expf(x[(size_t)o * LDC + t] - mx);
        y[(size_t)o * LDC + t] = (km && g_opt_mask[n*LO + o]) ? e * inv : 0.f;
    }
}

// ---------------------------------------------------------------------------
// Concat builders + final max
// ---------------------------------------------------------------------------
__global__ void k_feats()
{
    size_t idx = (size_t)blockIdx.x * 256 + threadIdx.x;
    size_t r = idx >> 10;
    int h = (int)(idx & 1023);
    int n = (int)(r >> 8);
    int o = (int)(r & 255);
    float cur = g_opt_enc[idx];
    float* xr = g_X + r * (7*HD);
    xr[h] = cur;
#pragma unroll
    for (int jj = 0; jj < 3; jj++) {
        float a = g_attnOpt[(((size_t)(n*3 + jj) * LO + o) << 10) + h];
        xr[(1 + 2*jj)*HD + h] = cur * a;
        xr[(2 + 2*jj)*HD + h] = cur - a;
    }
}

__global__ void k_concat2()
{
    size_t idx = (size_t)blockIdx.x * 256 + threadIdx.x;
    size_t r = idx >> 10;
    int h = (int)(idx & 1023);
    float* xr = g_X + r * (2*HD);
    xr[h] = g_opt_enc[idx];
    xr[HD + h] = g_corr[idx];
}

__global__ void k_concat3()
{
    size_t idx = (size_t)blockIdx.x * 256 + threadIdx.x;
    size_t r = idx >> 10;
    int h = (int)(idx & 1023);
    float* xr = g_X + r * (3*HD);
    xr[h] = g_option[idx];
    xr[HD + h] = g_attnD[idx];
    xr[2*HD + h] = g_coattn[idx];
}

__global__ void k_concat4()
{
    size_t idx = (size_t)blockIdx.x * 256 + threadIdx.x;
    size_t r = idx >> 10;
    int h = (int)(idx & 1023);
    float f = g_fusion[idx];
    float a = g_attn2[idx];
    float* xr = g_X + r * (4*HD);
    xr[h] = f;
    xr[HD + h] = a;
    xr[2*HD + h] = f * a;
    xr[3*HD + h] = f - a;
}

__global__ void k_final(float* __restrict__ out)
{
    int n = blockIdx.y;
    int h = blockIdx.x * 256 + threadIdx.x;
    float mx = NEGV;
    for (int o = 0; o < LO; o++) {
        if (g_opt_mask[n*LO + o])
            mx = fmaxf(mx, g_fusion2[((size_t)(n*LO + o) << 10) + h]);
    }
    out[(size_t)n * HD + h] = mx;
}

// ---------------------------------------------------------------------------
// Launch
// ---------------------------------------------------------------------------
extern "C" void kernel_launch(void* const* d_in, const int* in_sizes, int n_in,
                              void* d_out, int out_size)
{
    const float* ll  = (const float*)d_in[0];
    const int*   am  = (const int*)d_in[1];
    const int*   fpw = (const int*)d_in[2];
    int base = (in_sizes[3] <= 8) ? 4 : 3;
    const float* attn_w1   = (const float*)d_in[base+0];
    const float* attn_w2   = (const float*)d_in[base+1];
    const float* attn_w3   = (const float*)d_in[base+2];
    const float* opt_w1    = (const float*)d_in[base+3];
    const float* opt_w2    = (const float*)d_in[base+4];
    const float* opt_w3    = (const float*)d_in[base+5];
    const float* self_w1   = (const float*)d_in[base+6];
    const float* self_w2   = (const float*)d_in[base+7];
    const float* self_w3   = (const float*)d_in[base+8];
    const float* attn_fc_w = (const float*)d_in[base+9];
    const float* attn_fc_b = (const float*)d_in[base+10];
    const float* comp_fc_w = (const float*)d_in[base+11];
    const float* comp_fc_b = (const float*)d_in[base+12];
    const float* gate_fc_w = (const float*)d_in[base+13];
    const float* gate_fc_b = (const float*)d_in[base+14];
    const float* self_fc_w = (const float*)d_in[base+15];
    const float* self_fc_b = (const float*)d_in[base+16];
    float* out = (float*)d_out;

    float *opt_enc, *doc_enc, *logitOpt, *attnOpt, *X, *corr, *option;
    float *logitD, *kq, *attnD, *cow, *coattn, *fusion, *logitS, *attn2, *fusion2;
    float *rowq, *rowk, *rowkd;
    int *opt_mask, *doc_mask;
    cudaGetSymbolAddress((void**)&opt_enc,  g_opt_enc);
    cudaGetSymbolAddress((void**)&doc_enc,  g_doc_enc);
    cudaGetSymbolAddress((void**)&logitOpt, g_logitOpt);
    cudaGetSymbolAddress((void**)&attnOpt,  g_attnOpt);
    cudaGetSymbolAddress((void**)&X,        g_X);
    cudaGetSymbolAddress((void**)&corr,     g_corr);
    cudaGetSymbolAddress((void**)&option,   g_option);
    cudaGetSymbolAddress((void**)&logitD,   g_logitD);
    cudaGetSymbolAddress((void**)&kq,       g_kq);
    cudaGetSymbolAddress((void**)&attnD,    g_attnD);
    cudaGetSymbolAddress((void**)&cow,      g_cow);
    cudaGetSymbolAddress((void**)&coattn,   g_coattn);
    cudaGetSymbolAddress((void**)&fusion,   g_fusion);
    cudaGetSymbolAddress((void**)&logitS,   g_logitS);
    cudaGetSymbolAddress((void**)&attn2,    g_attn2);
    cudaGetSymbolAddress((void**)&fusion2,  g_fusion2);
    cudaGetSymbolAddress((void**)&rowq,     g_rowq);
    cudaGetSymbolAddress((void**)&rowk,     g_rowk);
    cudaGetSymbolAddress((void**)&rowkd,    g_rowkd);
    cudaGetSymbolAddress((void**)&opt_mask, g_opt_mask);
    cudaGetSymbolAddress((void**)&doc_mask, g_doc_mask);

    const int EW_BLOCKS = (MR * HD) / 256;   // 65536
    const dim3 FC_GRID(HD/128, MR/128);      // 8 x 128

    // 1) build encodings + masks
    k_build_opt<<<dim3(LO,  NRW), 256>>>(ll, am, fpw);
    k_build_doc<<<dim3(LDC, NRW), 256>>>(ll, am, fpw);

    // 2) opt-opt cross attention (192 pairs)
    k_rowdot<<<MR, 256>>>(opt_enc, opt_w1, rowq);
    k_rowdot<<<MR, 256>>>(opt_enc, opt_w2, rowk);
    k_mma<4,1><<<dim3(2, 2, NPAIR), 256>>>(
        opt_enc, opt_enc, logitOpt, LO, LO, HD, 0, 0,0,0,
        opt_w3, nullptr, rowq, rowk, opt_mask, opt_mask, 0,0, nullptr,nullptr, 1);
    k_row_softmax<<<dim3(LO, NPAIR), 256>>>(logitOpt, LO, opt_mask, opt_mask, 0,0,0, 1);
    k_mma<0,0><<<dim3(8, 2, NPAIR), 256>>>(
        logitOpt, opt_enc, attnOpt, LO, HD, LO, HD, 0,0,0,
        nullptr, nullptr, nullptr,nullptr,nullptr,nullptr, 0,0, nullptr,nullptr, 2);

    // 3) comp FC (K = 7H)
    k_feats<<<EW_BLOCKS, 256>>>();
    k_mma<1,1><<<FC_GRID, 256>>>(
        X, comp_fc_w, corr, MR, HD, 7*HD, 0, 0,0,0,
        nullptr, comp_fc_b, nullptr,nullptr,nullptr,nullptr, 0,0, nullptr,nullptr, 0);

    // 4) gate FC (K = 2H) with fused gate-combine -> option
    k_concat2<<<EW_BLOCKS, 256>>>();
    k_mma<3,1><<<FC_GRID, 256>>>(
        X, gate_fc_w, option, MR, HD, 2*HD, 0, 0,0,0,
        nullptr, gate_fc_b, nullptr,nullptr,nullptr,nullptr, 0,0, opt_enc, corr, 0);

    // 5) doc attention (with co-attention)
    k_rowdot<<<MR, 256>>>(option, attn_w1, rowq);
    k_rowdot<<<NRW*LDC, 256>>>(doc_enc, attn_w2, rowkd);
    k_mma<4,1><<<dim3(LDC/128, 2, NRW), 256>>>(
        option, doc_enc, logitD, LO, LDC, HD, 0,
        (long)LO*HD, (long)LDC*HD, (long)LO*LDC,
        attn_w3, nullptr, rowq, rowkd, opt_mask, doc_mask, LO, LDC, nullptr,nullptr, 0);
    k_col_softmax<<<dim3(LDC/256, NRW), 256>>>();
    k_row_softmax<<<dim3(LO, NRW), 256>>>(logitD, LDC, opt_mask, doc_mask,
        (long)LO*LDC, LO, LDC, 0);
    k_mma<0,0><<<dim3(8, 2, NRW), 256>>>(
        logitD, doc_enc, attnD, LO, HD, LDC, HD,
        (long)LO*LDC, (long)LDC*HD, (long)LO*HD,
        nullptr, nullptr, nullptr,nullptr,nullptr,nullptr, 0,0, nullptr,nullptr, 0);
    k_mma<0,1><<<dim3(2, 2, NRW), 256>>>(
        logitD, kq, cow, LO, LO, LDC, 0,
        (long)LO*LDC, (long)LO*LDC, (long)LO*LO,
        nullptr, nullptr, nullptr,nullptr,nullptr,nullptr, 0,0, nullptr,nullptr, 0);
    k_mma<0,0><<<dim3(8, 2, NRW), 256>>>(
        cow, option, coattn, LO, HD, LO, HD,
        (long)LO*LO, (long)LO*HD, (long)LO*HD,
        nullptr, nullptr, nullptr,nullptr,nullptr,nullptr, 0,0, nullptr,nullptr, 0);

    // 6) attn FC (K = 3H) -> fusion
    k_concat3<<<EW_BLOCKS, 256>>>();
    k_mma<1,1><<<FC_GRID, 256>>>(
        X, attn_fc_w, fusion, MR, HD, 3*HD, 0, 0,0,0,
        nullptr, attn_fc_b, nullptr,nullptr,nullptr,nullptr, 0,0, nullptr,nullptr, 0);

    // 7) self attention
    k_rowdot<<<MR, 256>>>(fusion, self_w1, rowq);
    k_rowdot<<<MR, 256>>>(fusion, self_w2, rowk);
    k_mma<4,1><<<dim3(2, 2, NRW), 256>>>(
        fusion, fusion, logitS, LO, LO, HD, 0,
        (long)LO*HD, (long)LO*HD, (long)LO*LO,
        self_w3, nullptr, rowq, rowk, opt_mask, opt_mask, LO, LO, nullptr,nullptr, 0);
    k_row_softmax<<<dim3(LO, NRW), 256>>>(logitS, LO, opt_mask, opt_mask,
        (long)LO*LO, LO, LO, 0);
    k_mma<0,0><<<dim3(8, 2, NRW), 256>>>(
        logitS, fusion, attn2, LO, HD, LO, HD,
        (long)LO*LO, (long)LO*HD, (long)LO*HD,
        nullptr, nullptr, nullptr,nullptr,nullptr,nullptr, 0,0, nullptr,nullptr, 0);

    // 8) self FC (K = 4H) -> fusion2
    k_concat4<<<EW_BLOCKS, 256>>>();
    k_mma<2,1><<<FC_GRID, 256>>>(
        X, self_fc_w, fusion2, MR, HD, 4*HD, 0, 0,0,0,
        nullptr, self_fc_b, nullptr,nullptr,nullptr,nullptr, 0,0, nullptr,nullptr, 0);

    // 9) masked max over option positions
    k_final<<<dim3(HD/256, NRW), 256>>>(out);
}

// round 11
// speedup vs baseline: 1.3289x; 1.3289x over previous
#include <cuda_runtime.h>
#include <cuda_fp16.h>
#include <math.h>
#include <stdint.h>

#define HD    1024
#define NL4   4
#define SEQ   512
#define NRW   64
#define LO    256
#define LDC   512
#define NPAIR (NRW*3)
#define MR    (NRW*LO)
#define NEGV  -1e30f

// ---------------------------------------------------------------------------
// Static device scratch
// ---------------------------------------------------------------------------
__device__ float g_opt_enc[MR*HD];
__device__ int   g_opt_mask[MR];
__device__ float g_doc_enc[NRW*LDC*HD];
__device__ int   g_doc_mask[NRW*LDC];
__device__ float g_logitOpt[NPAIR*LO*LO];
__device__ float g_attnOpt[NPAIR*LO*HD];
__device__ float g_X[MR*7*HD];
__device__ float g_corr[MR*HD];
__device__ float g_option[MR*HD];
__device__ float g_logitD[NRW*LO*LDC];
__device__ float g_kq[NRW*LO*LDC];
__device__ float g_attnD[MR*HD];
__device__ float g_cow[NRW*LO*LO];
__device__ float g_coattn[MR*HD];
__device__ float g_fusion[MR*HD];
__device__ float g_logitS[NRW*LO*LO];
__device__ float g_attn2[MR*HD];
__device__ float g_fusion2[MR*HD];
__device__ float g_rowq[MR];
__device__ float g_rowk[MR];
__device__ float g_rowkd[NRW*LDC];

// ---------------------------------------------------------------------------
// Helpers
// ---------------------------------------------------------------------------
__device__ __forceinline__ int read_fp(const int* __restrict__ p, int n)
{
    return (p[1] == 0) ? p[2*n] : p[n];   // int64 vs int32 sniff (values 300..450)
}

__device__ __forceinline__ void mma_f16(float* c, const uint32_t* a, const uint32_t* b)
{
    asm volatile(
        "mma.sync.aligned.m16n8k16.row.col.f32.f16.f16.f32 "
        "{%0,%1,%2,%3}, {%4,%5,%6,%7}, {%8,%9}, {%0,%1,%2,%3};"
        : "+f"(c[0]), "+f"(c[1]), "+f"(c[2]), "+f"(c[3])
        : "r"(a[0]), "r"(a[1]), "r"(a[2]), "r"(a[3]), "r"(b[0]), "r"(b[1]));
}

__device__ __forceinline__ uint32_t h2u(float a, float b)
{
    __half2 h = __floats2half2_rn(a, b);
    return *(uint32_t*)&h;
}

// ---------------------------------------------------------------------------
// Build kernels
// ---------------------------------------------------------------------------
__global__ void k_build_opt(const float* __restrict__ ll, const int* __restrict__ am,
                            const int* __restrict__ fpw)
{
    int o = blockIdx.x, n = blockIdx.y, t = threadIdx.x;
    int fp = read_fp(fpw, n);
    int idx = fp + o;
    int valid = (idx >= 0) && (idx < SEQ);
    int idxc = valid ? idx : (SEQ - 1);
    int m = valid && (am[n*SEQ + idxc] > 0);
    const float4* src = (const float4*)(ll + (size_t)(n*SEQ + idxc) * HD);
    float4* dst = (float4*)(g_opt_enc + (size_t)(n*LO + o) * HD);
    float4 v = m ? src[t] : make_float4(0.f,0.f,0.f,0.f);
    dst[t] = v;
    if (t == 0) g_opt_mask[n*LO + o] = m;
}

__global__ void k_build_doc(const float* __restrict__ ll, const int* __restrict__ am,
                            const int* __restrict__ fpw)
{
    int t0 = blockIdx.x, n = blockIdx.y, t = threadIdx.x;
    int fp = read_fp(fpw, n);
    int m = (t0 < fp) && (am[n*SEQ + t0] > 0);
    const float4* src = (const float4*)(ll + (size_t)(n*SEQ + t0) * HD);
    float4* dst = (float4*)(g_doc_enc + (size_t)(n*LDC + t0) * HD);
    float4 v = m ? src[t] : make_float4(0.f,0.f,0.f,0.f);
    dst[t] = v;
    if (t == 0) g_doc_mask[n*LDC + t0] = m;
}

__global__ void k_rowdot(const float* __restrict__ X, const float* __restrict__ w,
                         float* __restrict__ out)
{
    int r = blockIdx.x;
    const float* x = X + (size_t)r * HD;
    float s = 0.f;
    for (int i = threadIdx.x; i < HD; i += 256) s += x[i] * w[i];
    __shared__ float sh[256];
    sh[threadIdx.x] = s; __syncthreads();
    for (int st = 128; st > 0; st >>= 1) {
        if (threadIdx.x < st) sh[threadIdx.x] += sh[threadIdx.x + st];
        __syncthreads();
    }
    if (threadIdx.x == 0) out[r] = sh[0];
}

// ---------------------------------------------------------------------------
// fp32 SGEMMs (attention path) — unchanged from the 13.5ms baseline
// ---------------------------------------------------------------------------
template<int EPI>   // 0=none 4=trilinear logits
__global__ __launch_bounds__(256) void k_gemm_nt(
    const float* __restrict__ A, const float* __restrict__ B, float* __restrict__ C,
    int M, int N, int K,
    long sA, long sB, long sC,
    const float* __restrict__ colScale,
    const float* __restrict__ ql, const float* __restrict__ kl,
    const int* __restrict__ mq, const int* __restrict__ mk,
    long sQl, long sKl,
    int pairMode)
{
    __shared__ float As[8][128];
    __shared__ float Bs[8][128];
    const int z = blockIdx.z;
    long offA, offB, offC, offQl, offKl;
    if (pairMode) {
        int n = z / 3, jj = z % 3;
        int b = n / NL4, i = n % NL4;
        int j = jj + (jj >= i ? 1 : 0);
        int mb = b * NL4 + j;
        offA = (long)n * LO * HD; offB = (long)mb * LO * HD;
        offC = (long)z * M * N;
        offQl = (long)n * LO; offKl = (long)mb * LO;
    } else {
        offA = z * sA; offB = z * sB; offC = z * sC;
        offQl = z * sQl; offKl = z * sKl;
    }
    const float* Ab = A + offA;
    const float* Bb = B + offB;
    const int tid = threadIdx.x;
    const int bm = blockIdx.y * 128, bn = blockIdx.x * 128;
    const int lr = tid >> 1, lc = (tid & 1) * 4;
    const int ty = tid >> 4, tx = tid & 15;
    float acc[8][8];
#pragma unroll
    for (int i = 0; i < 8; i++)
#pragma unroll
        for (int j = 0; j < 8; j++) acc[i][j] = 0.f;

    for (int k0 = 0; k0 < K; k0 += 8) {
        float4 av = *(const float4*)(Ab + (size_t)(bm + lr) * K + k0 + lc);
        float4 bv = *(const float4*)(Bb + (size_t)(bn + lr) * K + k0 + lc);
        if (EPI == 4) {
            bv.x *= colScale[k0 + lc];     bv.y *= colScale[k0 + lc + 1];
            bv.z *= colScale[k0 + lc + 2]; bv.w *= colScale[k0 + lc + 3];
        }
        As[lc][lr] = av.x; As[lc+1][lr] = av.y; As[lc+2][lr] = av.z; As[lc+3][lr] = av.w;
        Bs[lc][lr] = bv.x; Bs[lc+1][lr] = bv.y; Bs[lc+2][lr] = bv.z; Bs[lc+3][lr] = bv.w;
        __syncthreads();
#pragma unroll
        for (int kk = 0; kk < 8; kk++) {
            float a[8], b[8];
#pragma unroll
            for (int u = 0; u < 8; u++) { a[u] = As[kk][ty*8+u]; b[u] = Bs[kk][tx*8+u]; }
#pragma unroll
            for (int i = 0; i < 8; i++)
#pragma unroll
                for (int j = 0; j < 8; j++) acc[i][j] += a[i] * b[j];
        }
        __syncthreads();
    }
#pragma unroll
    for (int i = 0; i < 8; i++) {
        int m = bm + ty * 8 + i;
#pragma unroll
        for (int j = 0; j < 8; j++) {
            int nn = bn + tx * 8 + j;
            size_t ci = (size_t)offC + (size_t)m * N + nn;
            float v = acc[i][j];
            if (EPI == 0) C[ci] = v;
            else {
                v += ql[offQl + m] + kl[offKl + nn];
                C[ci] = (mq[offQl + m] && mk[offKl + nn]) ? v : NEGV;
            }
        }
    }
}

__global__ __launch_bounds__(256) void k_gemm_nn(
    const float* __restrict__ A, const float* __restrict__ B, float* __restrict__ C,
    int M, int N, int K, long sA, long sB, long sC, int pairMode)
{
    __shared__ float As[8][128];
    __shared__ float Bs[8][128];
    int z = blockIdx.z;
    long offA, offB, offC;
    if (pairMode) {
        int n = z / 3, jj = z % 3;
        int b = n / NL4, i = n % NL4;
        int j = jj + (jj >= i ? 1 : 0);
        int mb = b * NL4 + j;
        offA = (long)z * LO * LO; offB = (long)mb * LO * HD; offC = (long)z * LO * HD;
    } else { offA = z * sA; offB = z * sB; offC = z * sC; }
    const float* Ab = A + offA;
    const float* Bb = B + offB;
    int tid = threadIdx.x;
    int bm = blockIdx.y * 128, bn = blockIdx.x * 128;
    int lr = tid >> 1, lc = (tid & 1) * 4;
    int br = tid >> 5, bc = (tid & 31) * 4;
    int ty = tid >> 4, tx = tid & 15;
    float acc[8][8];
#pragma unroll
    for (int i = 0; i < 8; i++)
#pragma unroll
        for (int j = 0; j < 8; j++) acc[i][j] = 0.f;

    for (int k0 = 0; k0 < K; k0 += 8) {
        float4 av = *(const float4*)(Ab + (size_t)(bm + lr) * K + k0 + lc);
        As[lc][lr] = av.x; As[lc+1][lr] = av.y; As[lc+2][lr] = av.z; As[lc+3][lr] = av.w;
        float4 bv = *(const float4*)(Bb + (size_t)(k0 + br) * N + bn + bc);
        *(float4*)&Bs[br][bc] = bv;
        __syncthreads();
#pragma unroll
        for (int kk = 0; kk < 8; kk++) {
            float a[8], b[8];
#pragma unroll
            for (int u = 0; u < 8; u++) { a[u] = As[kk][ty*8+u]; b[u] = Bs[kk][tx*8+u]; }
#pragma unroll
            for (int i = 0; i < 8; i++)
#pragma unroll
                for (int j = 0; j < 8; j++) acc[i][j] += a[i] * b[j];
        }
        __syncthreads();
    }
#pragma unroll
    for (int i = 0; i < 8; i++) {
        int m = bm + ty * 8 + i;
#pragma unroll
        for (int j = 0; j < 8; j++) {
            int nn = bn + tx * 8 + j;
            C[(size_t)offC + (size_t)m * N + nn] = acc[i][j];
        }
    }
}

// ---------------------------------------------------------------------------
// 2xFP16 mma.sync FC GEMM: C[MR,HD] = act(X[MR,K] @ W[HD,K]^T + bias)
// A = hi + lo (fp16 each, exact to ~22 bits); B single rn fp16.
// x*w ~= hi*w16 + lo*w16  (B rounding error ~2^-12, random sign -> ~1e-4 dot)
// BM=BN=128, BK=16, 8 warps (2m x 4n), 64x32 warp tiles, m16n8k16 HMMA.
// smem planes [k-pair t][row r] of half2, pair stride 544B: conflict-free.
// EPI: 1=tanh(+bias) 2=relu(+bias) 3=sigmoid gate: C = E1*g + E2*(1-g)
// ---------------------------------------------------------------------------
#define PT    544                  // bytes between k-pair planes' rows
#define PLANE (8*PT)               // 4352 B (8 k-pairs x 128 rows x half2)
#define BUFB  (3*PLANE)            // Ahi, Alo, Bhi

template<int EPI>
__global__ __launch_bounds__(256, 1) void k_fc_mma(
    const float* __restrict__ A, const float* __restrict__ Bw,
    float* __restrict__ C, int K,
    const float* __restrict__ bias,
    const float* __restrict__ E1, const float* __restrict__ E2)
{
    __shared__ __align__(16) char sm[2*BUFB];   // 26112 B
    const int tid = threadIdx.x;
    const int lane = tid & 31, wid = tid >> 5;
    const int wm = wid & 1, wn = wid >> 1;
    const int g = lane >> 2, t = lane & 3;
    const int bm = blockIdx.y << 7, bn = blockIdx.x << 7;

    float acc[4][4][4];
#pragma unroll
    for (int i = 0; i < 4; i++)
#pragma unroll
        for (int q = 0; q < 4; q++)
#pragma unroll
            for (int c = 0; c < 4; c++) acc[i][q][c] = 0.f;

    // Producer: threads 0..127 own one A row, 128..255 one B row (16 k each).
    const int prow = tid & 127;
    const bool isA = tid < 128;
    const float* gsrc = isA ? (A  + (size_t)(bm + prow) * K)
                            : (Bw + (size_t)(bn + prow) * K);
    float4 st[4];

    auto fetch = [&](int ch) {
        const float* p = gsrc + (ch << 4);
#pragma unroll
        for (int q = 0; q < 4; q++) st[q] = *(const float4*)(p + (q << 2));
    };
    auto store_buf = [&](int buf) {
        const float* v = (const float*)st;
        if (isA) {
            char* d = sm + buf*BUFB + prow*4;
#pragma unroll
            for (int tt = 0; tt < 8; ++tt) {
                float x0 = v[2*tt], x1 = v[2*tt + 1];
                __half2 h = __floats2half2_rn(x0, x1);
                float l0 = x0 - __half2float(__low2half(h));
                float l1 = x1 - __half2float(__high2half(h));
                *(uint32_t*)(d + tt*PT) = *(uint32_t*)&h;          // hi plane
                *(uint32_t*)(d + PLANE + tt*PT) = h2u(l0, l1);     // lo plane
            }
        } else {
            char* d = sm + buf*BUFB + 2*PLANE + prow*4;
#pragma unroll
            for (int tt = 0; tt < 8; ++tt)
                *(uint32_t*)(d + tt*PT) = h2u(v[2*tt], v[2*tt + 1]);  // hi only
        }
    };

    const int T = K >> 4;
    fetch(0);
    store_buf(0);
    __syncthreads();

    for (int ch = 0; ch < T; ++ch) {
        const int buf = ch & 1;
        if (ch + 1 < T) fetch(ch + 1);

        const char* Ah = sm + buf*BUFB;
        const char* Al = Ah + PLANE;
        const char* Bh = Ah + 2*PLANE;
        const int rA = (wm << 6) + g;
        const int rB = (wn << 5) + g;

        uint32_t ah[4][4], al[4][4], bh[4][2];
#pragma unroll
        for (int i = 0; i < 4; i++) {
            const char* p = Ah + t*PT + (rA + (i << 4)) * 4;
            ah[i][0] = *(const uint32_t*)p;
            ah[i][1] = *(const uint32_t*)(p + 32);          // row + 8
            ah[i][2] = *(const uint32_t*)(p + 4*PT);        // k-pair t+4
            ah[i][3] = *(const uint32_t*)(p + 4*PT + 32);
        }
#pragma unroll
        for (int q = 0; q < 4; q++) {
            const char* p = Bh + t*PT + (rB + (q << 3)) * 4;
            bh[q][0] = *(const uint32_t*)p;
            bh[q][1] = *(const uint32_t*)(p + 4*PT);
        }
#pragma unroll
        for (int i = 0; i < 4; i++)
#pragma unroll
            for (int q = 0; q < 4; q++) mma_f16(acc[i][q], ah[i], bh[q]);
#pragma unroll
        for (int i = 0; i < 4; i++) {
            const char* p = Al + t*PT + (rA + (i << 4)) * 4;
            al[i][0] = *(const uint32_t*)p;
            al[i][1] = *(const uint32_t*)(p + 32);
            al[i][2] = *(const uint32_t*)(p + 4*PT);
            al[i][3] = *(const uint32_t*)(p + 4*PT + 32);
        }
#pragma unroll
        for (int i = 0; i < 4; i++)
#pragma unroll
            for (int q = 0; q < 4; q++) mma_f16(acc[i][q], al[i], bh[q]);

        __syncthreads();
        if (ch + 1 < T) store_buf(buf ^ 1);
        __syncthreads();
    }

    // Epilogue
#pragma unroll
    for (int i = 0; i < 4; i++) {
        int row0 = bm + (wm << 6) + (i << 4) + g;
#pragma unroll
        for (int q = 0; q < 4; q++) {
            int col = bn + (wn << 5) + (q << 3) + (t << 1);
            float b0 = bias[col], b1 = bias[col + 1];
#pragma unroll
            for (int h = 0; h < 2; h++) {
                int row = row0 + h * 8;
                float v0 = acc[i][q][h*2+0] + b0;
                float v1 = acc[i][q][h*2+1] + b1;
                size_t ci = (size_t)row * HD + col;
                float2 o;
                if (EPI == 1)      { o.x = tanhf(v0);        o.y = tanhf(v1); }
                else if (EPI == 2) { o.x = fmaxf(v0, 0.f);   o.y = fmaxf(v1, 0.f); }
                else {
                    float g0 = 1.f / (1.f + expf(-v0));
                    float g1 = 1.f / (1.f + expf(-v1));
                    o.x = E1[ci]   * g0 + E2[ci]   * (1.f - g0);
                    o.y = E1[ci+1] * g1 + E2[ci+1] * (1.f - g1);
                }
                *(float2*)(C + ci) = o;
            }
        }
    }
}

// ---------------------------------------------------------------------------
// Softmax kernels
// ---------------------------------------------------------------------------
__global__ void k_row_softmax(float* __restrict__ X, int Cdim,
    const int* __restrict__ mqb, const int* __restrict__ mkb,
    long sX, long sMq, long sMk, int pairMode)
{
    int z = blockIdx.y, row = blockIdx.x;
    long offX, offMq, offMk;
    if (pairMode) {
        int n = z / 3, jj = z % 3;
        int b = n / NL4, i = n % NL4;
        int j = jj + (jj >= i ? 1 : 0);
        int mb = b * NL4 + j;
        offX = (long)z * LO * LO; offMq = (long)n * LO; offMk = (long)mb * LO;
    } else { offX = z * sX; offMq = z * sMq; offMk = z * sMk; }
    float* x = X + offX + (long)row * Cdim;
    const int* mk = mkb + offMk;
    int qm = mqb[offMq + row];
    int tid = threadIdx.x;
    __shared__ float sh[256];
    float mx = -3.4e38f;
    for (int c = tid; c < Cdim; c += 256) mx = fmaxf(mx, x[c]);
    sh[tid] = mx; __syncthreads();
    for (int s = 128; s > 0; s >>= 1) {
        if (tid < s) sh[tid] = fmaxf(sh[tid], sh[tid + s]);
        __syncthreads();
    }
    mx = sh[0]; __syncthreads();
    float sum = 0.f;
    for (int c = tid; c < Cdim; c += 256) sum += expf(x[c] - mx);
    sh[tid] = sum; __syncthreads();
    for (int s = 128; s > 0; s >>= 1) {
        if (tid < s) sh[tid] += sh[tid + s];
        __syncthreads();
    }
    float inv = 1.f / sh[0];
    for (int c = tid; c < Cdim; c += 256) {
        float e = expf(x[c] - mx);
        x[c] = (qm && mk[c]) ? e * inv : 0.f;
    }
}

__global__ void k_col_softmax()
{
    int n = blockIdx.y;
    int t = blockIdx.x * 256 + threadIdx.x;
    const float* x = g_logitD + (size_t)n * LO * LDC;
    float mx = -3.4e38f;
    for (int o = 0; o < LO; o++) mx = fmaxf(mx, x[(size_t)o * LDC + t]);
    float sum = 0.f;
    for (int o = 0; o < LO; o++) sum += expf(x[(size_t)o * LDC + t] - mx);
    float inv = 1.f / sum;
    int km = g_doc_mask[n*LDC + t];
    float* y = g_kq + (size_t)n * LO * LDC;
    for (int o = 0; o < LO; o++) {
        float e = expf(x[(size_t)o * LDC + t] - mx);
        y[(size_t)o * LDC + t] = (km && g_opt_mask[n*LO + o]) ? e * inv : 0.f;
    }
}

// ---------------------------------------------------------------------------
// Concat builders + final max
// ---------------------------------------------------------------------------
__global__ void k_feats()
{
    size_t idx = (size_t)blockIdx.x * 256 + threadIdx.x;
    size_t r = idx >> 10;
    int h = (int)(idx & 1023);
    int n = (int)(r >> 8);
    int o = (int)(r & 255);
    float cur = g_opt_enc[idx];
    float* xr = g_X + r * (7*HD);
    xr[h] = cur;
#pragma unroll
    for (int jj = 0; jj < 3; jj++) {
        float a = g_attnOpt[(((size_t)(n*3 + jj) * LO + o) << 10) + h];
        xr[(1 + 2*jj)*HD + h] = cur * a;
        xr[(2 + 2*jj)*HD + h] = cur - a;
    }
}

__global__ void k_concat2()
{
    size_t idx = (size_t)blockIdx.x * 256 + threadIdx.x;
    size_t r = idx >> 10;
    int h = (int)(idx & 1023);
    float* xr = g_X + r * (2*HD);
    xr[h] = g_opt_enc[idx];
    xr[HD + h] = g_corr[idx];
}

__global__ void k_concat3()
{
    size_t idx = (size_t)blockIdx.x * 256 + threadIdx.x;
    size_t r = idx >> 10;
    int h = (int)(idx & 1023);
    float* xr = g_X + r * (3*HD);
    xr[h] = g_option[idx];
    xr[HD + h] = g_attnD[idx];
    xr[2*HD + h] = g_coattn[idx];
}

__global__ void k_concat4()
{
    size_t idx = (size_t)blockIdx.x * 256 + threadIdx.x;
    size_t r = idx >> 10;
    int h = (int)(idx & 1023);
    float f = g_fusion[idx];
    float a = g_attn2[idx];
    float* xr = g_X + r * (4*HD);
    xr[h] = f;
    xr[HD + h] = a;
    xr[2*HD + h] = f * a;
    xr[3*HD + h] = f - a;
}

__global__ void k_final(float* __restrict__ out)
{
    int n = blockIdx.y;
    int h = blockIdx.x * 256 + threadIdx.x;
    float mx = NEGV;
    for (int o = 0; o < LO; o++) {
        if (g_opt_mask[n*LO + o])
            mx = fmaxf(mx, g_fusion2[((size_t)(n*LO + o) << 10) + h]);
    }
    out[(size_t)n * HD + h] = mx;
}

// ---------------------------------------------------------------------------
// Launch
// ---------------------------------------------------------------------------
extern "C" void kernel_launch(void* const* d_in, const int* in_sizes, int n_in,
                              void* d_out, int out_size)
{
    const float* ll  = (const float*)d_in[0];
    const int*   am  = (const int*)d_in[1];
    const int*   fpw = (const int*)d_in[2];
    int base = (in_sizes[3] <= 8) ? 4 : 3;
    const float* attn_w1   = (const float*)d_in[base+0];
    const float* attn_w2   = (const float*)d_in[base+1];
    const float* attn_w3   = (const float*)d_in[base+2];
    const float* opt_w1    = (const float*)d_in[base+3];
    const float* opt_w2    = (const float*)d_in[base+4];
    const float* opt_w3    = (const float*)d_in[base+5];
    const float* self_w1   = (const float*)d_in[base+6];
    const float* self_w2   = (const float*)d_in[base+7];
    const float* self_w3   = (const float*)d_in[base+8];
    const float* attn_fc_w = (const float*)d_in[base+9];
    const float* attn_fc_b = (const float*)d_in[base+10];
    const float* comp_fc_w = (const float*)d_in[base+11];
    const float* comp_fc_b = (const float*)d_in[base+12];
    const float* gate_fc_w = (const float*)d_in[base+13];
    const float* gate_fc_b = (const float*)d_in[base+14];
    const float* self_fc_w = (const float*)d_in[base+15];
    const float* self_fc_b = (const float*)d_in[base+16];
    float* out = (float*)d_out;

    float *opt_enc, *doc_enc, *logitOpt, *attnOpt, *X, *corr, *option;
    float *logitD, *kq, *attnD, *cow, *coattn, *fusion, *logitS, *attn2, *fusion2;
    float *rowq, *rowk, *rowkd;
    int *opt_mask, *doc_mask;
    cudaGetSymbolAddress((void**)&opt_enc,  g_opt_enc);
    cudaGetSymbolAddress((void**)&doc_enc,  g_doc_enc);
    cudaGetSymbolAddress((void**)&logitOpt, g_logitOpt);
    cudaGetSymbolAddress((void**)&attnOpt,  g_attnOpt);
    cudaGetSymbolAddress((void**)&X,        g_X);
    cudaGetSymbolAddress((void**)&corr,     g_corr);
    cudaGetSymbolAddress((void**)&option,   g_option);
    cudaGetSymbolAddress((void**)&logitD,   g_logitD);
    cudaGetSymbolAddress((void**)&kq,       g_kq);
    cudaGetSymbolAddress((void**)&attnD,    g_attnD);
    cudaGetSymbolAddress((void**)&cow,      g_cow);
    cudaGetSymbolAddress((void**)&coattn,   g_coattn);
    cudaGetSymbolAddress((void**)&fusion,   g_fusion);
    cudaGetSymbolAddress((void**)&logitS,   g_logitS);
    cudaGetSymbolAddress((void**)&attn2,    g_attn2);
    cudaGetSymbolAddress((void**)&fusion2,  g_fusion2);
    cudaGetSymbolAddress((void**)&rowq,     g_rowq);
    cudaGetSymbolAddress((void**)&rowk,     g_rowk);
    cudaGetSymbolAddress((void**)&rowkd,    g_rowkd);
    cudaGetSymbolAddress((void**)&opt_mask, g_opt_mask);
    cudaGetSymbolAddress((void**)&doc_mask, g_doc_mask);

    const int EW_BLOCKS = (MR * HD) / 256;   // 65536
    const dim3 FC_GRID(HD/128, MR/128);      // 8 x 128

    // 1) build encodings + masks
    k_build_opt<<<dim3(LO,  NRW), 256>>>(ll, am, fpw);
    k_build_doc<<<dim3(LDC, NRW), 256>>>(ll, am, fpw);

    // 2) opt-opt cross attention (192 pairs)
    k_rowdot<<<MR, 256>>>(opt_enc, opt_w1, rowq);
    k_rowdot<<<MR, 256>>>(opt_enc, opt_w2, rowk);
    k_gemm_nt<4><<<dim3(LO/128, LO/128, NPAIR), 256>>>(
        opt_enc, opt_enc, logitOpt, LO, LO, HD, 0,0,0,
        opt_w3, rowq, rowk, opt_mask, opt_mask, 0,0, 1);
    k_row_softmax<<<dim3(LO, NPAIR), 256>>>(logitOpt, LO, opt_mask, opt_mask, 0,0,0, 1);
    k_gemm_nn<<<dim3(HD/128, LO/128, NPAIR), 256>>>(
        logitOpt, opt_enc, attnOpt, LO, HD, LO, 0,0,0, 1);

    // 3) comp FC (K = 7H) via 2xFP16 tensor path
    k_feats<<<EW_BLOCKS, 256>>>();
    k_fc_mma<1><<<FC_GRID, 256>>>(X, comp_fc_w, corr, 7*HD, comp_fc_b, nullptr, nullptr);

    // 4) gate FC (K = 2H) with fused gate-combine -> option
    k_concat2<<<EW_BLOCKS, 256>>>();
    k_fc_mma<3><<<FC_GRID, 256>>>(X, gate_fc_w, option, 2*HD, gate_fc_b, opt_enc, corr);

    // 5) doc attention (with co-attention)
    k_rowdot<<<MR, 256>>>(option, attn_w1, rowq);
    k_rowdot<<<NRW*LDC, 256>>>(doc_enc, attn_w2, rowkd);
    k_gemm_nt<4><<<dim3(LDC/128, LO/128, NRW), 256>>>(
        option, doc_enc, logitD, LO, LDC, HD,
        (long)LO*HD, (long)LDC*HD, (long)LO*LDC,
        attn_w3, rowq, rowkd, opt_mask, doc_mask, LO, LDC, 0);
    k_col_softmax<<<dim3(LDC/256, NRW), 256>>>();
    k_row_softmax<<<dim3(LO, NRW), 256>>>(logitD, LDC, opt_mask, doc_mask,
        (long)LO*LDC, LO, LDC, 0);
    k_gemm_nn<<<dim3(HD/128, LO/128, NRW), 256>>>(
        logitD, doc_enc, attnD, LO, HD, LDC,
        (long)LO*LDC, (long)LDC*HD, (long)LO*HD, 0);
    k_gemm_nt<0><<<dim3(LO/128, LO/128, NRW), 256>>>(
        logitD, kq, cow, LO, LO, LDC,
        (long)LO*LDC, (long)LO*LDC, (long)LO*LO,
        nullptr, nullptr, nullptr, nullptr, nullptr, 0,0, 0);
    k_gemm_nn<<<dim3(HD/128, LO/128, NRW), 256>>>(
        cow, option, coattn, LO, HD, LO,
        (long)LO*LO, (long)LO*HD, (long)LO*HD, 0);

    // 6) attn FC (K = 3H) -> fusion
    k_concat3<<<EW_BLOCKS, 256>>>();
    k_fc_mma<1><<<FC_GRID, 256>>>(X, attn_fc_w, fusion, 3*HD, attn_fc_b, nullptr, nullptr);

    // 7) self attention
    k_rowdot<<<MR, 256>>>(fusion, self_w1, rowq);
    k_rowdot<<<MR, 256>>>(fusion, self_w2, rowk);
    k_gemm_nt<4><<<dim3(LO/128, LO/128, NRW), 256>>>(
        fusion, fusion, logitS, LO, LO, HD,
        (long)LO*HD, (long)LO*HD, (long)LO*LO,
        self_w3, rowq, rowk, opt_mask, opt_mask, LO, LO, 0);
    k_row_softmax<<<dim3(LO, NRW), 256>>>(logitS, LO, opt_mask, opt_mask,
        (long)LO*LO, LO, LO, 0);
    k_gemm_nn<<<dim3(HD/128, LO/128, NRW), 256>>>(
        logitS, fusion, attn2, LO, HD, LO,
        (long)LO*LO, (long)LO*HD, (long)LO*HD, 0);

    // 8) self FC (K = 4H) -> fusion2
    k_concat4<<<EW_BLOCKS, 256>>>();
    k_fc_mma<2><<<FC_GRID, 256>>>(X, self_fc_w, fusion2, 4*HD, self_fc_b, nullptr, nullptr);

    // 9) masked max over option positions
    k_final<<<dim3(HD/256, NRW), 256>>>(out);
}

// round 12
// speedup vs baseline: 1.4879x; 1.1197x over previous
#include <cuda_runtime.h>
#include <cuda_fp16.h>
#include <math.h>
#include <stdint.h>

#define HD    1024
#define NL4   4
#define SEQ   512
#define NRW   64
#define LO    256
#define LDC   512
#define NPAIR (NRW*3)
#define MR    (NRW*LO)
#define NEGV  -1e30f

// ---------------------------------------------------------------------------
// Static device scratch
// ---------------------------------------------------------------------------
__device__ float g_opt_enc[MR*HD];
__device__ int   g_opt_mask[MR];
__device__ float g_doc_enc[NRW*LDC*HD];
__device__ int   g_doc_mask[NRW*LDC];
__device__ float g_logitOpt[NPAIR*LO*LO];
__device__ float g_attnOpt[NPAIR*LO*HD];
__device__ float g_X[MR*7*HD];
__device__ float g_corr[MR*HD];
__device__ float g_option[MR*HD];
__device__ float g_logitD[NRW*LO*LDC];
__device__ float g_kq[NRW*LO*LDC];
__device__ float g_attnD[MR*HD];
__device__ float g_cow[NRW*LO*LO];
__device__ float g_coattn[MR*HD];
__device__ float g_fusion[MR*HD];
__device__ float g_logitS[NRW*LO*LO];
__device__ float g_attn2[MR*HD];
__device__ float g_fusion2[MR*HD];
__device__ float g_rowq[MR];
__device__ float g_rowk[MR];
__device__ float g_rowkd[NRW*LDC];

// ---------------------------------------------------------------------------
// Helpers
// ---------------------------------------------------------------------------
__device__ __forceinline__ int read_fp(const int* __restrict__ p, int n)
{
    return (p[1] == 0) ? p[2*n] : p[n];   // int64 vs int32 sniff (values 300..450)
}

__device__ __forceinline__ void mma_f16(float* c, const uint32_t* a, const uint32_t* b)
{
    asm volatile(
        "mma.sync.aligned.m16n8k16.row.col.f32.f16.f16.f32 "
        "{%0,%1,%2,%3}, {%4,%5,%6,%7}, {%8,%9}, {%0,%1,%2,%3};"
        : "+f"(c[0]), "+f"(c[1]), "+f"(c[2]), "+f"(c[3])
        : "r"(a[0]), "r"(a[1]), "r"(a[2]), "r"(a[3]), "r"(b[0]), "r"(b[1]));
}

__device__ __forceinline__ uint32_t h2u(float a, float b)
{
    __half2 h = __floats2half2_rn(a, b);
    return *(uint32_t*)&h;
}

// ---------------------------------------------------------------------------
// Build kernels
// ---------------------------------------------------------------------------
__global__ void k_build_opt(const float* __restrict__ ll, const int* __restrict__ am,
                            const int* __restrict__ fpw)
{
    int o = blockIdx.x, n = blockIdx.y, t = threadIdx.x;
    int fp = read_fp(fpw, n);
    int idx = fp + o;
    int valid = (idx >= 0) && (idx < SEQ);
    int idxc = valid ? idx : (SEQ - 1);
    int m = valid && (am[n*SEQ + idxc] > 0);
    const float4* src = (const float4*)(ll + (size_t)(n*SEQ + idxc) * HD);
    float4* dst = (float4*)(g_opt_enc + (size_t)(n*LO + o) * HD);
    float4 v = m ? src[t] : make_float4(0.f,0.f,0.f,0.f);
    dst[t] = v;
    if (t == 0) g_opt_mask[n*LO + o] = m;
}

__global__ void k_build_doc(const float* __restrict__ ll, const int* __restrict__ am,
                            const int* __restrict__ fpw)
{
    int t0 = blockIdx.x, n = blockIdx.y, t = threadIdx.x;
    int fp = read_fp(fpw, n);
    int m = (t0 < fp) && (am[n*SEQ + t0] > 0);
    const float4* src = (const float4*)(ll + (size_t)(n*SEQ + t0) * HD);
    float4* dst = (float4*)(g_doc_enc + (size_t)(n*LDC + t0) * HD);
    float4 v = m ? src[t] : make_float4(0.f,0.f,0.f,0.f);
    dst[t] = v;
    if (t == 0) g_doc_mask[n*LDC + t0] = m;
}

__global__ void k_rowdot(const float* __restrict__ X, const float* __restrict__ w,
                         float* __restrict__ out)
{
    int r = blockIdx.x;
    const float* x = X + (size_t)r * HD;
    float s = 0.f;
    for (int i = threadIdx.x; i < HD; i += 256) s += x[i] * w[i];
    __shared__ float sh[256];
    sh[threadIdx.x] = s; __syncthreads();
    for (int st = 128; st > 0; st >>= 1) {
        if (threadIdx.x < st) sh[threadIdx.x] += sh[threadIdx.x + st];
        __syncthreads();
    }
    if (threadIdx.x == 0) out[r] = sh[0];
}

// ---------------------------------------------------------------------------
// fp32 SGEMMs (attention path) — unchanged
// ---------------------------------------------------------------------------
template<int EPI>   // 0=none 4=trilinear logits
__global__ __launch_bounds__(256) void k_gemm_nt(
    const float* __restrict__ A, const float* __restrict__ B, float* __restrict__ C,
    int M, int N, int K,
    long sA, long sB, long sC,
    const float* __restrict__ colScale,
    const float* __restrict__ ql, const float* __restrict__ kl,
    const int* __restrict__ mq, const int* __restrict__ mk,
    long sQl, long sKl,
    int pairMode)
{
    __shared__ float As[8][128];
    __shared__ float Bs[8][128];
    const int z = blockIdx.z;
    long offA, offB, offC, offQl, offKl;
    if (pairMode) {
        int n = z / 3, jj = z % 3;
        int b = n / NL4, i = n % NL4;
        int j = jj + (jj >= i ? 1 : 0);
        int mb = b * NL4 + j;
        offA = (long)n * LO * HD; offB = (long)mb * LO * HD;
        offC = (long)z * M * N;
        offQl = (long)n * LO; offKl = (long)mb * LO;
    } else {
        offA = z * sA; offB = z * sB; offC = z * sC;
        offQl = z * sQl; offKl = z * sKl;
    }
    const float* Ab = A + offA;
    const float* Bb = B + offB;
    const int tid = threadIdx.x;
    const int bm = blockIdx.y * 128, bn = blockIdx.x * 128;
    const int lr = tid >> 1, lc = (tid & 1) * 4;
    const int ty = tid >> 4, tx = tid & 15;
    float acc[8][8];
#pragma unroll
    for (int i = 0; i < 8; i++)
#pragma unroll
        for (int j = 0; j < 8; j++) acc[i][j] = 0.f;

    for (int k0 = 0; k0 < K; k0 += 8) {
        float4 av = *(const float4*)(Ab + (size_t)(bm + lr) * K + k0 + lc);
        float4 bv = *(const float4*)(Bb + (size_t)(bn + lr) * K + k0 + lc);
        if (EPI == 4) {
            bv.x *= colScale[k0 + lc];     bv.y *= colScale[k0 + lc + 1];
            bv.z *= colScale[k0 + lc + 2]; bv.w *= colScale[k0 + lc + 3];
        }
        As[lc][lr] = av.x; As[lc+1][lr] = av.y; As[lc+2][lr] = av.z; As[lc+3][lr] = av.w;
        Bs[lc][lr] = bv.x; Bs[lc+1][lr] = bv.y; Bs[lc+2][lr] = bv.z; Bs[lc+3][lr] = bv.w;
        __syncthreads();
#pragma unroll
        for (int kk = 0; kk < 8; kk++) {
            float a[8], b[8];
#pragma unroll
            for (int u = 0; u < 8; u++) { a[u] = As[kk][ty*8+u]; b[u] = Bs[kk][tx*8+u]; }
#pragma unroll
            for (int i = 0; i < 8; i++)
#pragma unroll
                for (int j = 0; j < 8; j++) acc[i][j] += a[i] * b[j];
        }
        __syncthreads();
    }
#pragma unroll
    for (int i = 0; i < 8; i++) {
        int m = bm + ty * 8 + i;
#pragma unroll
        for (int j = 0; j < 8; j++) {
            int nn = bn + tx * 8 + j;
            size_t ci = (size_t)offC + (size_t)m * N + nn;
            float v = acc[i][j];
            if (EPI == 0) C[ci] = v;
            else {
                v += ql[offQl + m] + kl[offKl + nn];
                C[ci] = (mq[offQl + m] && mk[offKl + nn]) ? v : NEGV;
            }
        }
    }
}

__global__ __launch_bounds__(256) void k_gemm_nn(
    const float* __restrict__ A, const float* __restrict__ B, float* __restrict__ C,
    int M, int N, int K, long sA, long sB, long sC, int pairMode)
{
    __shared__ float As[8][128];
    __shared__ float Bs[8][128];
    int z = blockIdx.z;
    long offA, offB, offC;
    if (pairMode) {
        int n = z / 3, jj = z % 3;
        int b = n / NL4, i = n % NL4;
        int j = jj + (jj >= i ? 1 : 0);
        int mb = b * NL4 + j;
        offA = (long)z * LO * LO; offB = (long)mb * LO * HD; offC = (long)z * LO * HD;
    } else { offA = z * sA; offB = z * sB; offC = z * sC; }
    const float* Ab = A + offA;
    const float* Bb = B + offB;
    int tid = threadIdx.x;
    int bm = blockIdx.y * 128, bn = blockIdx.x * 128;
    int lr = tid >> 1, lc = (tid & 1) * 4;
    int br = tid >> 5, bc = (tid & 31) * 4;
    int ty = tid >> 4, tx = tid & 15;
    float acc[8][8];
#pragma unroll
    for (int i = 0; i < 8; i++)
#pragma unroll
        for (int j = 0; j < 8; j++) acc[i][j] = 0.f;

    for (int k0 = 0; k0 < K; k0 += 8) {
        float4 av = *(const float4*)(Ab + (size_t)(bm + lr) * K + k0 + lc);
        As[lc][lr] = av.x; As[lc+1][lr] = av.y; As[lc+2][lr] = av.z; As[lc+3][lr] = av.w;
        float4 bv = *(const float4*)(Bb + (size_t)(k0 + br) * N + bn + bc);
        *(float4*)&Bs[br][bc] = bv;
        __syncthreads();
#pragma unroll
        for (int kk = 0; kk < 8; kk++) {
            float a[8], b[8];
#pragma unroll
            for (int u = 0; u < 8; u++) { a[u] = As[kk][ty*8+u]; b[u] = Bs[kk][tx*8+u]; }
#pragma unroll
            for (int i = 0; i < 8; i++)
#pragma unroll
                for (int j = 0; j < 8; j++) acc[i][j] += a[i] * b[j];
        }
        __syncthreads();
    }
#pragma unroll
    for (int i = 0; i < 8; i++) {
        int m = bm + ty * 8 + i;
#pragma unroll
        for (int j = 0; j < 8; j++) {
            int nn = bn + tx * 8 + j;
            C[(size_t)offC + (size_t)m * N + nn] = acc[i][j];
        }
    }
}

// ---------------------------------------------------------------------------
// 2xFP16 mma.sync FC GEMM: C[MR,HD] = act(X[MR,K] @ W[HD,K]^T + bias)
// A = hi + lo (fp16 each, exact to ~22 bits); B single rn fp16.
// ONE sync per chunk (double-buffer invariant: buffer X is read in chunks
// with ch&1==X and written in chunks with ch&1==X^1; the end-of-chunk
// barrier always separates read-of-X from the next write-of-X).
// 2 CTAs/SM for latency hiding (smem 26KB, regs capped at 128).
// EPI: 1=tanh(+bias) 2=relu(+bias) 3=sigmoid gate: C = E1*g + E2*(1-g)
// ---------------------------------------------------------------------------
#define PT    544                  // bytes between k-pair planes' rows
#define PLANE (8*PT)               // 4352 B (8 k-pairs x 128 rows x half2)
#define BUFB  (3*PLANE)            // Ahi, Alo, Bhi

template<int EPI>
__global__ __launch_bounds__(256, 2) void k_fc_mma(
    const float* __restrict__ A, const float* __restrict__ Bw,
    float* __restrict__ C, int K,
    const float* __restrict__ bias,
    const float* __restrict__ E1, const float* __restrict__ E2)
{
    __shared__ __align__(16) char sm[2*BUFB];   // 26112 B
    const int tid = threadIdx.x;
    const int lane = tid & 31, wid = tid >> 5;
    const int wm = wid & 1, wn = wid >> 1;
    const int g = lane >> 2, t = lane & 3;
    const int bm = blockIdx.y << 7, bn = blockIdx.x << 7;

    float acc[4][4][4];
#pragma unroll
    for (int i = 0; i < 4; i++)
#pragma unroll
        for (int q = 0; q < 4; q++)
#pragma unroll
            for (int c = 0; c < 4; c++) acc[i][q][c] = 0.f;

    // Producer: threads 0..127 own one A row, 128..255 one B row (16 k each).
    const int prow = tid & 127;
    const bool isA = tid < 128;
    const float* gsrc = isA ? (A  + (size_t)(bm + prow) * K)
                            : (Bw + (size_t)(bn + prow) * K);
    float4 st[4];

    auto fetch = [&](int ch) {
        const float* p = gsrc + (ch << 4);
#pragma unroll
        for (int q = 0; q < 4; q++) st[q] = *(const float4*)(p + (q << 2));
    };
    auto store_buf = [&](int buf) {
        const float* v = (const float*)st;
        if (isA) {
            char* d = sm + buf*BUFB + prow*4;
#pragma unroll
            for (int tt = 0; tt < 8; ++tt) {
                float x0 = v[2*tt], x1 = v[2*tt + 1];
                __half2 h = __floats2half2_rn(x0, x1);
                float l0 = x0 - __half2float(__low2half(h));
                float l1 = x1 - __half2float(__high2half(h));
                *(uint32_t*)(d + tt*PT) = *(uint32_t*)&h;          // hi plane
                *(uint32_t*)(d + PLANE + tt*PT) = h2u(l0, l1);     // lo plane
            }
        } else {
            char* d = sm + buf*BUFB + 2*PLANE + prow*4;
#pragma unroll
            for (int tt = 0; tt < 8; ++tt)
                *(uint32_t*)(d + tt*PT) = h2u(v[2*tt], v[2*tt + 1]);  // hi only
        }
    };

    const int T = K >> 4;
    fetch(0);
    store_buf(0);
    __syncthreads();

    for (int ch = 0; ch < T; ++ch) {
        const int buf = ch & 1;
        if (ch + 1 < T) fetch(ch + 1);

        const char* Ah = sm + buf*BUFB;
        const char* Al = Ah + PLANE;
        const char* Bh = Ah + 2*PLANE;
        const int rA = (wm << 6) + g;
        const int rB = (wn << 5) + g;

        uint32_t ah[4][4], al[4][4], bh[4][2];
#pragma unroll
        for (int i = 0; i < 4; i++) {
            const char* p = Ah + t*PT + (rA + (i << 4)) * 4;
            ah[i][0] = *(const uint32_t*)p;
            ah[i][1] = *(const uint32_t*)(p + 32);          // row + 8
            ah[i][2] = *(const uint32_t*)(p + 4*PT);        // k-pair t+4
            ah[i][3] = *(const uint32_t*)(p + 4*PT + 32);
        }
#pragma unroll
        for (int q = 0; q < 4; q++) {
            const char* p = Bh + t*PT + (rB + (q << 3)) * 4;
            bh[q][0] = *(const uint32_t*)p;
            bh[q][1] = *(const uint32_t*)(p + 4*PT);
        }
#pragma unroll
        for (int i = 0; i < 4; i++)
#pragma unroll
            for (int q = 0; q < 4; q++) mma_f16(acc[i][q], ah[i], bh[q]);
#pragma unroll
        for (int i = 0; i < 4; i++) {
            const char* p = Al + t*PT + (rA + (i << 4)) * 4;
            al[i][0] = *(const uint32_t*)p;
            al[i][1] = *(const uint32_t*)(p + 32);
            al[i][2] = *(const uint32_t*)(p + 4*PT);
            al[i][3] = *(const uint32_t*)(p + 4*PT + 32);
        }
#pragma unroll
        for (int i = 0; i < 4; i++)
#pragma unroll
            for (int q = 0; q < 4; q++) mma_f16(acc[i][q], al[i], bh[q]);

        // Producer store overlaps other warps' MMA; one barrier per chunk.
        if (ch + 1 < T) store_buf(buf ^ 1);
        __syncthreads();
    }

    // Epilogue
#pragma unroll
    for (int i = 0; i < 4; i++) {
        int row0 = bm + (wm << 6) + (i << 4) + g;
#pragma unroll
        for (int q = 0; q < 4; q++) {
            int col = bn + (wn << 5) + (q << 3) + (t << 1);
            float b0 = bias[col], b1 = bias[col + 1];
#pragma unroll
            for (int h = 0; h < 2; h++) {
                int row = row0 + h * 8;
                float v0 = acc[i][q][h*2+0] + b0;
                float v1 = acc[i][q][h*2+1] + b1;
                size_t ci = (size_t)row * HD + col;
                float2 o;
                if (EPI == 1)      { o.x = tanhf(v0);        o.y = tanhf(v1); }
                else if (EPI == 2) { o.x = fmaxf(v0, 0.f);   o.y = fmaxf(v1, 0.f); }
                else {
                    float g0 = 1.f / (1.f + expf(-v0));
                    float g1 = 1.f / (1.f + expf(-v1));
                    o.x = E1[ci]   * g0 + E2[ci]   * (1.f - g0);
                    o.y = E1[ci+1] * g1 + E2[ci+1] * (1.f - g1);
                }
                *(float2*)(C + ci) = o;
            }
        }
    }
}

// ---------------------------------------------------------------------------
// Softmax kernels
// ---------------------------------------------------------------------------
__global__ void k_row_softmax(float* __restrict__ X, int Cdim,
    const int* __restrict__ mqb, const int* __restrict__ mkb,
    long sX, long sMq, long sMk, int pairMode)
{
    int z = blockIdx.y, row = blockIdx.x;
    long offX, offMq, offMk;
    if (pairMode) {
        int n = z / 3, jj = z % 3;
        int b = n / NL4, i = n % NL4;
        int j = jj + (jj >= i ? 1 : 0);
        int mb = b * NL4 + j;
        offX = (long)z * LO * LO; offMq = (long)n * LO; offMk = (long)mb * LO;
    } else { offX = z * sX; offMq = z * sMq; offMk = z * sMk; }
    float* x = X + offX + (long)row * Cdim;
    const int* mk = mkb + offMk;
    int qm = mqb[offMq + row];
    int tid = threadIdx.x;
    __shared__ float sh[256];
    float mx = -3.4e38f;
    for (int c = tid; c < Cdim; c += 256) mx = fmaxf(mx, x[c]);
    sh[tid] = mx; __syncthreads();
    for (int s = 128; s > 0; s >>= 1) {
        if (tid < s) sh[tid] = fmaxf(sh[tid], sh[tid + s]);
        __syncthreads();
    }
    mx = sh[0]; __syncthreads();
    float sum = 0.f;
    for (int c = tid; c < Cdim; c += 256) sum += expf(x[c] - mx);
    sh[tid] = sum; __syncthreads();
    for (int s = 128; s > 0; s >>= 1) {
        if (tid < s) sh[tid] += sh[tid + s];
        __syncthreads();
    }
    float inv = 1.f / sh[0];
    for (int c = tid; c < Cdim; c += 256) {
        float e = expf(x[c] - mx);
        x[c] = (qm && mk[c]) ? e * inv : 0.f;
    }
}

__global__ void k_col_softmax()
{
    int n = blockIdx.y;
    int t = blockIdx.x * 256 + threadIdx.x;
    const float* x = g_logitD + (size_t)n * LO * LDC;
    float mx = -3.4e38f;
    for (int o = 0; o < LO; o++) mx = fmaxf(mx, x[(size_t)o * LDC + t]);
    float sum = 0.f;
    for (int o = 0; o < LO; o++) sum += expf(x[(size_t)o * LDC + t] - mx);
    float inv = 1.f / sum;
    int km = g_doc_mask[n*LDC + t];
    float* y = g_kq + (size_t)n * LO * LDC;
    for (int o = 0; o < LO; o++) {
        float e = expf(x[(size_t)o * LDC + t] - mx);
        y[(size_t)o * LDC + t] = (km && g_opt_mask[n*LO + o]) ? e * inv : 0.f;
    }
}

// ---------------------------------------------------------------------------
// Concat builders + final max
// ---------------------------------------------------------------------------
__global__ void k_feats()
{
    size_t idx = (size_t)blockIdx.x * 256 + threadIdx.x;
    size_t r = idx >> 10;
    int h = (int)(idx & 1023);
    int n = (int)(r >> 8);
    int o = (int)(r & 255);
    float cur = g_opt_enc[idx];
    float* xr = g_X + r * (7*HD);
    xr[h] = cur;
#pragma unroll
    for (int jj = 0; jj < 3; jj++) {
        float a = g_attnOpt[(((size_t)(n*3 + jj) * LO + o) << 10) + h];
        xr[(1 + 2*jj)*HD + h] = cur * a;
        xr[(2 + 2*jj)*HD + h] = cur - a;
    }
}

__global__ void k_concat2()
{
    size_t idx = (size_t)blockIdx.x * 256 + threadIdx.x;
    size_t r = idx >> 10;
    int h = (int)(idx & 1023);
    float* xr = g_X + r * (2*HD);
    xr[h] = g_opt_enc[idx];
    xr[HD + h] = g_corr[idx];
}

__global__ void k_concat3()
{
    size_t idx = (size_t)blockIdx.x * 256 + threadIdx.x;
    size_t r = idx >> 10;
    int h = (int)(idx & 1023);
    float* xr = g_X + r * (3*HD);
    xr[h] = g_option[idx];
    xr[HD + h] = g_attnD[idx];
    xr[2*HD + h] = g_coattn[idx];
}

__global__ void k_concat4()
{
    size_t idx = (size_t)blockIdx.x * 256 + threadIdx.x;
    size_t r = idx >> 10;
    int h = (int)(idx & 1023);
    float f = g_fusion[idx];
    float a = g_attn2[idx];
    float* xr = g_X + r * (4*HD);
    xr[h] = f;
    xr[HD + h] = a;
    xr[2*HD + h] = f * a;
    xr[3*HD + h] = f - a;
}

__global__ void k_final(float* __restrict__ out)
{
    int n = blockIdx.y;
    int h = blockIdx.x * 256 + threadIdx.x;
    float mx = NEGV;
    for (int o = 0; o < LO; o++) {
        if (g_opt_mask[n*LO + o])
            mx = fmaxf(mx, g_fusion2[((size_t)(n*LO + o) << 10) + h]);
    }
    out[(size_t)n * HD + h] = mx;
}

// ---------------------------------------------------------------------------
// Launch
// ---------------------------------------------------------------------------
extern "C" void kernel_launch(void* const* d_in, const int* in_sizes, int n_in,
                              void* d_out, int out_size)
{
    const float* ll  = (const float*)d_in[0];
    const int*   am  = (const int*)d_in[1];
    const int*   fpw = (const int*)d_in[2];
    int base = (in_sizes[3] <= 8) ? 4 : 3;
    const float* attn_w1   = (const float*)d_in[base+0];
    const float* attn_w2   = (const float*)d_in[base+1];
    const float* attn_w3   = (const float*)d_in[base+2];
    const float* opt_w1    = (const float*)d_in[base+3];
    const float* opt_w2    = (const float*)d_in[base+4];
    const float* opt_w3    = (const float*)d_in[base+5];
    const float* self_w1   = (const float*)d_in[base+6];
    const float* self_w2   = (const float*)d_in[base+7];
    const float* self_w3   = (const float*)d_in[base+8];
    const float* attn_fc_w = (const float*)d_in[base+9];
    const float* attn_fc_b = (const float*)d_in[base+10];
    const float* comp_fc_w = (const float*)d_in[base+11];
    const float* comp_fc_b = (const float*)d_in[base+12];
    const float* gate_fc_w = (const float*)d_in[base+13];
    const float* gate_fc_b = (const float*)d_in[base+14];
    const float* self_fc_w = (const float*)d_in[base+15];
    const float* self_fc_b = (const float*)d_in[base+16];
    float* out = (float*)d_out;

    float *opt_enc, *doc_enc, *logitOpt, *attnOpt, *X, *corr, *option;
    float *logitD, *kq, *attnD, *cow, *coattn, *fusion, *logitS, *attn2, *fusion2;
    float *rowq, *rowk, *rowkd;
    int *opt_mask, *doc_mask;
    cudaGetSymbolAddress((void**)&opt_enc,  g_opt_enc);
    cudaGetSymbolAddress((void**)&doc_enc,  g_doc_enc);
    cudaGetSymbolAddress((void**)&logitOpt, g_logitOpt);
    cudaGetSymbolAddress((void**)&attnOpt,  g_attnOpt);
    cudaGetSymbolAddress((void**)&X,        g_X);
    cudaGetSymbolAddress((void**)&corr,     g_corr);
    cudaGetSymbolAddress((void**)&option,   g_option);
    cudaGetSymbolAddress((void**)&logitD,   g_logitD);
    cudaGetSymbolAddress((void**)&kq,       g_kq);
    cudaGetSymbolAddress((void**)&attnD,    g_attnD);
    cudaGetSymbolAddress((void**)&cow,      g_cow);
    cudaGetSymbolAddress((void**)&coattn,   g_coattn);
    cudaGetSymbolAddress((void**)&fusion,   g_fusion);
    cudaGetSymbolAddress((void**)&logitS,   g_logitS);
    cudaGetSymbolAddress((void**)&attn2,    g_attn2);
    cudaGetSymbolAddress((void**)&fusion2,  g_fusion2);
    cudaGetSymbolAddress((void**)&rowq,     g_rowq);
    cudaGetSymbolAddress((void**)&rowk,     g_rowk);
    cudaGetSymbolAddress((void**)&rowkd,    g_rowkd);
    cudaGetSymbolAddress((void**)&opt_mask, g_opt_mask);
    cudaGetSymbolAddress((void**)&doc_mask, g_doc_mask);

    const int EW_BLOCKS = (MR * HD) / 256;   // 65536
    const dim3 FC_GRID(HD/128, MR/128);      // 8 x 128

    // 1) build encodings + masks
    k_build_opt<<<dim3(LO,  NRW), 256>>>(ll, am, fpw);
    k_build_doc<<<dim3(LDC, NRW), 256>>>(ll, am, fpw);

    // 2) opt-opt cross attention (192 pairs)
    k_rowdot<<<MR, 256>>>(opt_enc, opt_w1, rowq);
    k_rowdot<<<MR, 256>>>(opt_enc, opt_w2, rowk);
    k_gemm_nt<4><<<dim3(LO/128, LO/128, NPAIR), 256>>>(
        opt_enc, opt_enc, logitOpt, LO, LO, HD, 0,0,0,
        opt_w3, rowq, rowk, opt_mask, opt_mask, 0,0, 1);
    k_row_softmax<<<dim3(LO, NPAIR), 256>>>(logitOpt, LO, opt_mask, opt_mask, 0,0,0, 1);
    k_gemm_nn<<<dim3(HD/128, LO/128, NPAIR), 256>>>(
        logitOpt, opt_enc, attnOpt, LO, HD, LO, 0,0,0, 1);

    // 3) comp FC (K = 7H) via 2xFP16 tensor path
    k_feats<<<EW_BLOCKS, 256>>>();
    k_fc_mma<1><<<FC_GRID, 256>>>(X, comp_fc_w, corr, 7*HD, comp_fc_b, nullptr, nullptr);

    // 4) gate FC (K = 2H) with fused gate-combine -> option
    k_concat2<<<EW_BLOCKS, 256>>>();
    k_fc_mma<3><<<FC_GRID, 256>>>(X, gate_fc_w, option, 2*HD, gate_fc_b, opt_enc, corr);

    // 5) doc attention (with co-attention)
    k_rowdot<<<MR, 256>>>(option, attn_w1, rowq);
    k_rowdot<<<NRW*LDC, 256>>>(doc_enc, attn_w2, rowkd);
    k_gemm_nt<4><<<dim3(LDC/128, LO/128, NRW), 256>>>(
        option, doc_enc, logitD, LO, LDC, HD,
        (long)LO*HD, (long)LDC*HD, (long)LO*LDC,
        attn_w3, rowq, rowkd, opt_mask, doc_mask, LO, LDC, 0);
    k_col_softmax<<<dim3(LDC/256, NRW), 256>>>();
    k_row_softmax<<<dim3(LO, NRW), 256>>>(logitD, LDC, opt_mask, doc_mask,
        (long)LO*LDC, LO, LDC, 0);
    k_gemm_nn<<<dim3(HD/128, LO/128, NRW), 256>>>(
        logitD, doc_enc, attnD, LO, HD, LDC,
        (long)LO*LDC, (long)LDC*HD, (long)LO*HD, 0);
    k_gemm_nt<0><<<dim3(LO/128, LO/128, NRW), 256>>>(
        logitD, kq, cow, LO, LO, LDC,
        (long)LO*LDC, (long)LO*LDC, (long)LO*LO,
        nullptr, nullptr, nullptr, nullptr, nullptr, 0,0, 0);
    k_gemm_nn<<<dim3(HD/128, LO/128, NRW), 256>>>(
        cow, option, coattn, LO, HD, LO,
        (long)LO*LO, (long)LO*HD, (long)LO*HD, 0);

    // 6) attn FC (K = 3H) -> fusion
    k_concat3<<<EW_BLOCKS, 256>>>();
    k_fc_mma<1><<<FC_GRID, 256>>>(X, attn_fc_w, fusion, 3*HD, attn_fc_b, nullptr, nullptr);

    // 7) self attention
    k_rowdot<<<MR, 256>>>(fusion, self_w1, rowq);
    k_rowdot<<<MR, 256>>>(fusion, self_w2, rowk);
    k_gemm_nt<4><<<dim3(LO/128, LO/128, NRW), 256>>>(
        fusion, fusion, logitS, LO, LO, HD,
        (long)LO*HD, (long)LO*HD, (long)LO*LO,
        self_w3, rowq, rowk, opt_mask, opt_mask, LO, LO, 0);
    k_row_softmax<<<dim3(LO, NRW), 256>>>(logitS, LO, opt_mask, opt_mask,
        (long)LO*LO, LO, LO, 0);
    k_gemm_nn<<<dim3(HD/128, LO/128, NRW), 256>>>(
        logitS, fusion, attn2, LO, HD, LO,
        (long)LO*LO, (long)LO*HD, (long)LO*HD, 0);

    // 8) self FC (K = 4H) -> fusion2
    k_concat4<<<EW_BLOCKS, 256>>>();
    k_fc_mma<2><<<FC_GRID, 256>>>(X, self_fc_w, fusion2, 4*HD, self_fc_b, nullptr, nullptr);

    // 9) masked max over option positions
    k_final<<<dim3(HD/256, NRW), 256>>>(out);
}

// round 14
// speedup vs baseline: 1.6105x; 1.0824x over previous
#include <cuda_runtime.h>
#include <cuda_fp16.h>
#include <math.h>
#include <stdint.h>

#define HD    1024
#define NL4   4
#define SEQ   512
#define NRW   64
#define LO    256
#define LDC   512
#define NPAIR (NRW*3)
#define MR    (NRW*LO)
#define NEGV  -1e30f

// ---------------------------------------------------------------------------
// Static device scratch
// ---------------------------------------------------------------------------
__device__ float  g_opt_enc[MR*HD];
__device__ int    g_opt_mask[MR];
__device__ float  g_doc_enc[NRW*LDC*HD];
__device__ int    g_doc_mask[NRW*LDC];
__device__ float  g_logitOpt[NPAIR*LO*LO];
__device__ float  g_attnOpt[NPAIR*LO*HD];
__device__ __half g_Xh[MR*7*HD];          // FC input, hi fp16 plane (224 MB)
__device__ __half g_Xl[MR*7*HD];          // FC input, lo fp16 plane (224 MB)
__device__ __half g_Wh[16*HD*HD];         // fp16 weights: comp|gate|attn|self (32 MB)
__device__ float  g_corr[MR*HD];
__device__ float  g_option[MR*HD];
__device__ float  g_logitD[NRW*LO*LDC];
__device__ float  g_kq[NRW*LO*LDC];
__device__ float  g_attnD[MR*HD];
__device__ float  g_cow[NRW*LO*LO];
__device__ float  g_coattn[MR*HD];
__device__ float  g_fusion[MR*HD];
__device__ float  g_logitS[NRW*LO*LO];
__device__ float  g_attn2[MR*HD];
__device__ float  g_fusion2[MR*HD];
__device__ float  g_rowq[MR];
__device__ float  g_rowk[MR];
__device__ float  g_rowkd[NRW*LDC];

// ---------------------------------------------------------------------------
// Helpers
// ---------------------------------------------------------------------------
__device__ __forceinline__ int read_fp(const int* __restrict__ p, int n)
{
    return (p[1] == 0) ? p[2*n] : p[n];   // int64 vs int32 sniff (values 300..450)
}

__device__ __forceinline__ void mma_f16(float* c, const uint32_t* a, const uint32_t* b)
{
    asm volatile(
        "mma.sync.aligned.m16n8k16.row.col.f32.f16.f16.f32 "
        "{%0,%1,%2,%3}, {%4,%5,%6,%7}, {%8,%9}, {%0,%1,%2,%3};"
        : "+f"(c[0]), "+f"(c[1]), "+f"(c[2]), "+f"(c[3])
        : "r"(a[0]), "r"(a[1]), "r"(a[2]), "r"(a[3]), "r"(b[0]), "r"(b[1]));
}

// hi/lo split write (identical rounding to the R11 in-kernel split)
__device__ __forceinline__ void wsplit(__half* __restrict__ xh, __half* __restrict__ xl,
                                       size_t i, float x)
{
    __half h = __float2half_rn(x);
    xh[i] = h;
    xl[i] = __float2half_rn(x - __half2float(h));
}

// ---------------------------------------------------------------------------
// Build kernels
// ---------------------------------------------------------------------------
__global__ void k_build_opt(const float* __restrict__ ll, const int* __restrict__ am,
                            const int* __restrict__ fpw)
{
    int o = blockIdx.x, n = blockIdx.y, t = threadIdx.x;
    int fp = read_fp(fpw, n);
    int idx = fp + o;
    int valid = (idx >= 0) && (idx < SEQ);
    int idxc = valid ? idx : (SEQ - 1);
    int m = valid && (am[n*SEQ + idxc] > 0);
    const float4* src = (const float4*)(ll + (size_t)(n*SEQ + idxc) * HD);
    float4* dst = (float4*)(g_opt_enc + (size_t)(n*LO + o) * HD);
    float4 v = m ? src[t] : make_float4(0.f,0.f,0.f,0.f);
    dst[t] = v;
    if (t == 0) g_opt_mask[n*LO + o] = m;
}

__global__ void k_build_doc(const float* __restrict__ ll, const int* __restrict__ am,
                            const int* __restrict__ fpw)
{
    int t0 = blockIdx.x, n = blockIdx.y, t = threadIdx.x;
    int fp = read_fp(fpw, n);
    int m = (t0 < fp) && (am[n*SEQ + t0] > 0);
    const float4* src = (const float4*)(ll + (size_t)(n*SEQ + t0) * HD);
    float4* dst = (float4*)(g_doc_enc + (size_t)(n*LDC + t0) * HD);
    float4 v = m ? src[t] : make_float4(0.f,0.f,0.f,0.f);
    dst[t] = v;
    if (t == 0) g_doc_mask[n*LDC + t0] = m;
}

__global__ void k_rowdot(const float* __restrict__ X, const float* __restrict__ w,
                         float* __restrict__ out)
{
    int r = blockIdx.x;
    const float* x = X + (size_t)r * HD;
    float s = 0.f;
    for (int i = threadIdx.x; i < HD; i += 256) s += x[i] * w[i];
    __shared__ float sh[256];
    sh[threadIdx.x] = s; __syncthreads();
    for (int st = 128; st > 0; st >>= 1) {
        if (threadIdx.x < st) sh[threadIdx.x] += sh[threadIdx.x + st];
        __syncthreads();
    }
    if (threadIdx.x == 0) out[r] = sh[0];
}

// weight fp32 -> fp16 (rn), elementwise
__global__ void k_cvtw(const float* __restrict__ w, __half* __restrict__ o)
{
    int i = blockIdx.x * 256 + threadIdx.x;
    float4 v = ((const float4*)w)[i];
    __half2 h0 = __floats2half2_rn(v.x, v.y);
    __half2 h1 = __floats2half2_rn(v.z, v.w);
    ((__half2*)o)[2*i]   = h0;
    ((__half2*)o)[2*i+1] = h1;
}

// ---------------------------------------------------------------------------
// fp32 SGEMMs (attention path) — unchanged
// ---------------------------------------------------------------------------
template<int EPI>   // 0=none 4=trilinear logits
__global__ __launch_bounds__(256) void k_gemm_nt(
    const float* __restrict__ A, const float* __restrict__ B, float* __restrict__ C,
    int M, int N, int K,
    long sA, long sB, long sC,
    const float* __restrict__ colScale,
    const float* __restrict__ ql, const float* __restrict__ kl,
    const int* __restrict__ mq, const int* __restrict__ mk,
    long sQl, long sKl,
    int pairMode)
{
    __shared__ float As[8][128];
    __shared__ float Bs[8][128];
    const int z = blockIdx.z;
    long offA, offB, offC, offQl, offKl;
    if (pairMode) {
        int n = z / 3, jj = z % 3;
        int b = n / NL4, i = n % NL4;
        int j = jj + (jj >= i ? 1 : 0);
        int mb = b * NL4 + j;
        offA = (long)n * LO * HD; offB = (long)mb * LO * HD;
        offC = (long)z * M * N;
        offQl = (long)n * LO; offKl = (long)mb * LO;
    } else {
        offA = z * sA; offB = z * sB; offC = z * sC;
        offQl = z * sQl; offKl = z * sKl;
    }
    const float* Ab = A + offA;
    const float* Bb = B + offB;
    const int tid = threadIdx.x;
    const int bm = blockIdx.y * 128, bn = blockIdx.x * 128;
    const int lr = tid >> 1, lc = (tid & 1) * 4;
    const int ty = tid >> 4, tx = tid & 15;
    float acc[8][8];
#pragma unroll
    for (int i = 0; i < 8; i++)
#pragma unroll
        for (int j = 0; j < 8; j++) acc[i][j] = 0.f;

    for (int k0 = 0; k0 < K; k0 += 8) {
        float4 av = *(const float4*)(Ab + (size_t)(bm + lr) * K + k0 + lc);
        float4 bv = *(const float4*)(Bb + (size_t)(bn + lr) * K + k0 + lc);
        if (EPI == 4) {
            bv.x *= colScale[k0 + lc];     bv.y *= colScale[k0 + lc + 1];
            bv.z *= colScale[k0 + lc + 2]; bv.w *= colScale[k0 + lc + 3];
        }
        As[lc][lr] = av.x; As[lc+1][lr] = av.y; As[lc+2][lr] = av.z; As[lc+3][lr] = av.w;
        Bs[lc][lr] = bv.x; Bs[lc+1][lr] = bv.y; Bs[lc+2][lr] = bv.z; Bs[lc+3][lr] = bv.w;
        __syncthreads();
#pragma unroll
        for (int kk = 0; kk < 8; kk++) {
            float a[8], b[8];
#pragma unroll
            for (int u = 0; u < 8; u++) { a[u] = As[kk][ty*8+u]; b[u] = Bs[kk][tx*8+u]; }
#pragma unroll
            for (int i = 0; i < 8; i++)
#pragma unroll
                for (int j = 0; j < 8; j++) acc[i][j] += a[i] * b[j];
        }
        __syncthreads();
    }
#pragma unroll
    for (int i = 0; i < 8; i++) {
        int m = bm + ty * 8 + i;
#pragma unroll
        for (int j = 0; j < 8; j++) {
            int nn = bn + tx * 8 + j;
            size_t ci = (size_t)offC + (size_t)m * N + nn;
            float v = acc[i][j];
            if (EPI == 0) C[ci] = v;
            else {
                v += ql[offQl + m] + kl[offKl + nn];
                C[ci] = (mq[offQl + m] && mk[offKl + nn]) ? v : NEGV;
            }
        }
    }
}

__global__ __launch_bounds__(256) void k_gemm_nn(
    const float* __restrict__ A, const float* __restrict__ B, float* __restrict__ C,
    int M, int N, int K, long sA, long sB, long sC, int pairMode)
{
    __shared__ float As[8][128];
    __shared__ float Bs[8][128];
    int z = blockIdx.z;
    long offA, offB, offC;
    if (pairMode) {
        int n = z / 3, jj = z % 3;
        int b = n / NL4, i = n % NL4;
        int j = jj + (jj >= i ? 1 : 0);
        int mb = b * NL4 + j;
        offA = (long)z * LO * LO; offB = (long)mb * LO * HD; offC = (long)z * LO * HD;
    } else { offA = z * sA; offB = z * sB; offC = z * sC; }
    const float* Ab = A + offA;
    const float* Bb = B + offB;
    int tid = threadIdx.x;
    int bm = blockIdx.y * 128, bn = blockIdx.x * 128;
    int lr = tid >> 1, lc = (tid & 1) * 4;
    int br = tid >> 5, bc = (tid & 31) * 4;
    int ty = tid >> 4, tx = tid & 15;
    float acc[8][8];
#pragma unroll
    for (int i = 0; i < 8; i++)
#pragma unroll
        for (int j = 0; j < 8; j++) acc[i][j] = 0.f;

    for (int k0 = 0; k0 < K; k0 += 8) {
        float4 av = *(const float4*)(Ab + (size_t)(bm + lr) * K + k0 + lc);
        As[lc][lr] = av.x; As[lc+1][lr] = av.y; As[lc+2][lr] = av.z; As[lc+3][lr] = av.w;
        float4 bv = *(const float4*)(Bb + (size_t)(k0 + br) * N + bn + bc);
        *(float4*)&Bs[br][bc] = bv;
        __syncthreads();
#pragma unroll
        for (int kk = 0; kk < 8; kk++) {
            float a[8], b[8];
#pragma unroll
            for (int u = 0; u < 8; u++) { a[u] = As[kk][ty*8+u]; b[u] = Bs[kk][tx*8+u]; }
#pragma unroll
            for (int i = 0; i < 8; i++)
#pragma unroll
                for (int j = 0; j < 8; j++) acc[i][j] += a[i] * b[j];
        }
        __syncthreads();
    }
#pragma unroll
    for (int i = 0; i < 8; i++) {
        int m = bm + ty * 8 + i;
#pragma unroll
        for (int j = 0; j < 8; j++) {
            int nn = bn + tx * 8 + j;
            C[(size_t)offC + (size_t)m * N + nn] = acc[i][j];
        }
    }
}

// ---------------------------------------------------------------------------
// 2xFP16 mma.sync FC GEMM, pre-converted operands:
//   A hi/lo fp16 planes in global (g_Xh/g_Xl), W fp16 (g_Wh slice).
//   Producer is a pure uint4 copy into k-pair-plane smem — zero cvt.
// One barrier per chunk; 2 CTAs/SM. Math identical to R11 (same rn splits).
// EPI: 1=tanh(+bias) 2=relu(+bias) 3=sigmoid gate: C = E1*g + E2*(1-g)
// ---------------------------------------------------------------------------
#define PT    544                  // bytes between k-pair planes' rows
#define PLANE (8*PT)               // 4352 B (8 k-pairs x 128 rows x half2)
#define BUFB  (3*PLANE)            // Ahi, Alo, Bhi

template<int EPI>
__global__ __launch_bounds__(256, 2) void k_fc_mma(
    const __half* __restrict__ Ah_g, const __half* __restrict__ Al_g,
    const __half* __restrict__ Bw,
    float* __restrict__ C, int K,
    const float* __restrict__ bias,
    const float* __restrict__ E1, const float* __restrict__ E2)
{
    __shared__ __align__(16) char sm[2*BUFB];   // 26112 B
    const int tid = threadIdx.x;
    const int lane = tid & 31, wid = tid >> 5;
    const int wm = wid & 1, wn = wid >> 1;
    const int g = lane >> 2, t = lane & 3;
    const int bm = blockIdx.y << 7, bn = blockIdx.x << 7;

    float acc[4][4][4];
#pragma unroll
    for (int i = 0; i < 4; i++)
#pragma unroll
        for (int q = 0; q < 4; q++)
#pragma unroll
            for (int c = 0; c < 4; c++) acc[i][q][c] = 0.f;

    // Producer: threads 0..127 own one A row, 128..255 one B row (16 k each).
    const int prow = tid & 127;
    const bool isA = tid < 128;
    const __half* srcH = isA ? (Ah_g + (size_t)(bm + prow) * K)
                             : (Bw   + (size_t)(bn + prow) * K);
    const __half* srcL = Al_g + (size_t)(bm + prow) * K;   // used only if isA
    uint4 f0, f1, f2, f3;

    auto fetch = [&](int ch) {
        const __half* p = srcH + (ch << 4);
        f0 = *(const uint4*)p;
        f1 = *(const uint4*)(p + 8);
        if (isA) {
            const __half* q = srcL + (ch << 4);
            f2 = *(const uint4*)q;
            f3 = *(const uint4*)(q + 8);
        }
    };
    auto store_buf = [&](int buf) {
        char* d = sm + buf*BUFB + (isA ? 0 : 2*PLANE) + prow*4;
        *(uint32_t*)(d + 0*PT) = f0.x; *(uint32_t*)(d + 1*PT) = f0.y;
        *(uint32_t*)(d + 2*PT) = f0.z; *(uint32_t*)(d + 3*PT) = f0.w;
        *(uint32_t*)(d + 4*PT) = f1.x; *(uint32_t*)(d + 5*PT) = f1.y;
        *(uint32_t*)(d + 6*PT) = f1.z; *(uint32_t*)(d + 7*PT) = f1.w;
        if (isA) {
            char* dl = d + PLANE;
            *(uint32_t*)(dl + 0*PT) = f2.x; *(uint32_t*)(dl + 1*PT) = f2.y;
            *(uint32_t*)(dl + 2*PT) = f2.z; *(uint32_t*)(dl + 3*PT) = f2.w;
            *(uint32_t*)(dl + 4*PT) = f3.x; *(uint32_t*)(dl + 5*PT) = f3.y;
            *(uint32_t*)(dl + 6*PT) = f3.z; *(uint32_t*)(dl + 7*PT) = f3.w;
        }
    };

    const int T = K >> 4;
    fetch(0);
    store_buf(0);
    __syncthreads();

    for (int ch = 0; ch < T; ++ch) {
        const int buf = ch & 1;
        if (ch + 1 < T) fetch(ch + 1);

        const char* Ah = sm + buf*BUFB;
        const char* Al = Ah + PLANE;
        const char* Bh = Ah + 2*PLANE;
        const int rA = (wm << 6) + g;
        const int rB = (wn << 5) + g;

        uint32_t ah[4][4], al[4][4], bh[4][2];
#pragma unroll
        for (int i = 0; i < 4; i++) {
            const char* p = Ah + t*PT + (rA + (i << 4)) * 4;
            ah[i][0] = *(const uint32_t*)p;
            ah[i][1] = *(const uint32_t*)(p + 32);          // row + 8
            ah[i][2] = *(const uint32_t*)(p + 4*PT);        // k-pair t+4
            ah[i][3] = *(const uint32_t*)(p + 4*PT + 32);
        }
#pragma unroll
        for (int q = 0; q < 4; q++) {
            const char* p = Bh + t*PT + (rB + (q << 3)) * 4;
            bh[q][0] = *(const uint32_t*)p;
            bh[q][1] = *(const uint32_t*)(p + 4*PT);
        }
#pragma unroll
        for (int i = 0; i < 4; i++)
#pragma unroll
            for (int q = 0; q < 4; q++) mma_f16(acc[i][q], ah[i], bh[q]);
#pragma unroll
        for (int i = 0; i < 4; i++) {
            const char* p = Al + t*PT + (rA + (i << 4)) * 4;
            al[i][0] = *(const uint32_t*)p;
            al[i][1] = *(const uint32_t*)(p + 32);
            al[i][2] = *(const uint32_t*)(p + 4*PT);
            al[i][3] = *(const uint32_t*)(p + 4*PT + 32);
        }
#pragma unroll
        for (int i = 0; i < 4; i++)
#pragma unroll
            for (int q = 0; q < 4; q++) mma_f16(acc[i][q], al[i], bh[q]);

        // Producer store overlaps other warps' MMA; one barrier per chunk.
        if (ch + 1 < T) store_buf(buf ^ 1);
        __syncthreads();
    }

    // Epilogue
#pragma unroll
    for (int i = 0; i < 4; i++) {
        int row0 = bm + (wm << 6) + (i << 4) + g;
#pragma unroll
        for (int q = 0; q < 4; q++) {
            int col = bn + (wn << 5) + (q << 3) + (t << 1);
            float b0 = bias[col], b1 = bias[col + 1];
#pragma unroll
            for (int h = 0; h < 2; h++) {
                int row = row0 + h * 8;
                float v0 = acc[i][q][h*2+0] + b0;
                float v1 = acc[i][q][h*2+1] + b1;
                size_t ci = (size_t)row * HD + col;
                float2 o;
                if (EPI == 1)      { o.x = tanhf(v0);        o.y = tanhf(v1); }
                else if (EPI == 2) { o.x = fmaxf(v0, 0.f);   o.y = fmaxf(v1, 0.f); }
                else {
                    float g0 = 1.f / (1.f + expf(-v0));
                    float g1 = 1.f / (1.f + expf(-v1));
                    o.x = E1[ci]   * g0 + E2[ci]   * (1.f - g0);
                    o.y = E1[ci+1] * g1 + E2[ci+1] * (1.f - g1);
                }
                *(float2*)(C + ci) = o;
            }
        }
    }
}

// ---------------------------------------------------------------------------
// Softmax kernels
// ---------------------------------------------------------------------------
__global__ void k_row_softmax(float* __restrict__ X, int Cdim,
    const int* __restrict__ mqb, const int* __restrict__ mkb,
    long sX, long sMq, long sMk, int pairMode)
{
    int z = blockIdx.y, row = blockIdx.x;
    long offX, offMq, offMk;
    if (pairMode) {
        int n = z / 3, jj = z % 3;
        int b = n / NL4, i = n % NL4;
        int j = jj + (jj >= i ? 1 : 0);
        int mb = b * NL4 + j;
        offX = (long)z * LO * LO; offMq = (long)n * LO; offMk = (long)mb * LO;
    } else { offX = z * sX; offMq = z * sMq; offMk = z * sMk; }
    float* x = X + offX + (long)row * Cdim;
    const int* mk = mkb + offMk;
    int qm = mqb[offMq + row];
    int tid = threadIdx.x;
    __shared__ float sh[256];
    float mx = -3.4e38f;
    for (int c = tid; c < Cdim; c += 256) mx = fmaxf(mx, x[c]);
    sh[tid] = mx; __syncthreads();
    for (int s = 128; s > 0; s >>= 1) {
        if (tid < s) sh[tid] = fmaxf(sh[tid], sh[tid + s]);
        __syncthreads();
    }
    mx = sh[0]; __syncthreads();
    float sum = 0.f;
    for (int c = tid; c < Cdim; c += 256) sum += expf(x[c] - mx);
    sh[tid] = sum; __syncthreads();
    for (int s = 128; s > 0; s >>= 1) {
        if (tid < s) sh[tid] += sh[tid + s];
        __syncthreads();
    }
    float inv = 1.f / sh[0];
    for (int c = tid; c < Cdim; c += 256) {
        float e = expf(x[c] - mx);
        x[c] = (qm && mk[c]) ? e * inv : 0.f;
    }
}

__global__ void k_col_softmax()
{
    int n = blockIdx.y;
    int t = blockIdx.x * 256 + threadIdx.x;
    const float* x = g_logitD + (size_t)n * LO * LDC;
    float mx = -3.4e38f;
    for (int o = 0; o < LO; o++) mx = fmaxf(mx, x[(size_t)o * LDC + t]);
    float sum = 0.f;
    for (int o = 0; o < LO; o++) sum += expf(x[(size_t)o * LDC + t] - mx);
    float inv = 1.f / sum;
    int km = g_doc_mask[n*LDC + t];
    float* y = g_kq + (size_t)n * LO * LDC;
    for (int o = 0; o < LO; o++) {
        float e = expf(x[(size_t)o * LDC + t] - mx);
        y[(size_t)o * LDC + t] = (km && g_opt_mask[n*LO + o]) ? e * inv : 0.f;
    }
}

// ---------------------------------------------------------------------------
// Concat builders (emit hi/lo fp16 planes directly) + final max
// ---------------------------------------------------------------------------
__global__ void k_feats()
{
    size_t idx = (size_t)blockIdx.x * 256 + threadIdx.x;
    size_t r = idx >> 10;
    int h = (int)(idx & 1023);
    int n = (int)(r >> 8);
    int o = (int)(r & 255);
    float cur = g_opt_enc[idx];
    __half* xh = g_Xh + r * (7*HD);
    __half* xl = g_Xl + r * (7*HD);
    wsplit(xh, xl, h, cur);
#pragma unroll
    for (int jj = 0; jj < 3; jj++) {
        float a = g_attnOpt[(((size_t)(n*3 + jj) * LO + o) << 10) + h];
        wsplit(xh, xl, (size_t)(1 + 2*jj)*HD + h, cur * a);
        wsplit(xh, xl, (size_t)(2 + 2*jj)*HD + h, cur - a);
    }
}

__global__ void k_concat2()
{
    size_t idx = (size_t)blockIdx.x * 256 + threadIdx.x;
    size_t r = idx >> 10;
    int h = (int)(idx & 1023);
    __half* xh = g_Xh + r * (2*HD);
    __half* xl = g_Xl + r * (2*HD);
    wsplit(xh, xl, h, g_opt_enc[idx]);
    wsplit(xh, xl, (size_t)HD + h, g_corr[idx]);
}

__global__ void k_concat3()
{
    size_t idx = (size_t)blockIdx.x * 256 + threadIdx.x;
    size_t r = idx >> 10;
    int h = (int)(idx & 1023);
    __half* xh = g_Xh + r * (3*HD);
    __half* xl = g_Xl + r * (3*HD);
    wsplit(xh, xl, h, g_option[idx]);
    wsplit(xh, xl, (size_t)HD + h, g_attnD[idx]);
    wsplit(xh, xl, (size_t)2*HD + h, g_coattn[idx]);
}

__global__ void k_concat4()
{
    size_t idx = (size_t)blockIdx.x * 256 + threadIdx.x;
    size_t r = idx >> 10;
    int h = (int)(idx & 1023);
    float f = g_fusion[idx];
    float a = g_attn2[idx];
    __half* xh = g_Xh + r * (4*HD);
    __half* xl = g_Xl + r * (4*HD);
    wsplit(xh, xl, h, f);
    wsplit(xh, xl, (size_t)HD + h, a);
    wsplit(xh, xl, (size_t)2*HD + h, f * a);
    wsplit(xh, xl, (size_t)3*HD + h, f - a);
}

__global__ void k_final(float* __restrict__ out)
{
    int n = blockIdx.y;
    int h = blockIdx.x * 256 + threadIdx.x;
    float mx = NEGV;
    for (int o = 0; o < LO; o++) {
        if (g_opt_mask[n*LO + o])
            mx = fmaxf(mx, g_fusion2[((size_t)(n*LO + o) << 10) + h]);
    }
    out[(size_t)n * HD + h] = mx;
}

// ---------------------------------------------------------------------------
// Launch
// ---------------------------------------------------------------------------
extern "C" void kernel_launch(void* const* d_in, const int* in_sizes, int n_in,
                              void* d_out, int out_size)
{
    const float* ll  = (const float*)d_in[0];
    const int*   am  = (const int*)d_in[1];
    const int*   fpw = (const int*)d_in[2];
    int base = (in_sizes[3] <= 8) ? 4 : 3;
    const float* attn_w1   = (const float*)d_in[base+0];
    const float* attn_w2   = (const float*)d_in[base+1];
    const float* attn_w3   = (const float*)d_in[base+2];
    const float* opt_w1    = (const float*)d_in[base+3];
    const float* opt_w2    = (const float*)d_in[base+4];
    const float* opt_w3    = (const float*)d_in[base+5];
    const float* self_w1   = (const float*)d_in[base+6];
    const float* self_w2   = (const float*)d_in[base+7];
    const float* self_w3   = (const float*)d_in[base+8];
    const float* attn_fc_w = (const float*)d_in[base+9];
    const float* attn_fc_b = (const float*)d_in[base+10];
    const float* comp_fc_w = (const float*)d_in[base+11];
    const float* comp_fc_b = (const float*)d_in[base+12];
    const float* gate_fc_w = (const float*)d_in[base+13];
    const float* gate_fc_b = (const float*)d_in[base+14];
    const float* self_fc_w = (const float*)d_in[base+15];
    const float* self_fc_b = (const float*)d_in[base+16];
    float* out = (float*)d_out;

    float *opt_enc, *doc_enc, *logitOpt, *attnOpt, *corr, *option;
    float *logitD, *kq, *attnD, *cow, *coattn, *fusion, *logitS, *attn2, *fusion2;
    float *rowq, *rowk, *rowkd;
    __half *Xh, *Xl, *Wh;
    int *opt_mask, *doc_mask;
    cudaGetSymbolAddress((void**)&opt_enc,  g_opt_enc);
    cudaGetSymbolAddress((void**)&doc_enc,  g_doc_enc);
    cudaGetSymbolAddress((void**)&logitOpt, g_logitOpt);
    cudaGetSymbolAddress((void**)&attnOpt,  g_attnOpt);
    cudaGetSymbolAddress((void**)&Xh,       g_Xh);
    cudaGetSymbolAddress((void**)&Xl,       g_Xl);
    cudaGetSymbolAddress((void**)&Wh,       g_Wh);
    cudaGetSymbolAddress((void**)&corr,     g_corr);
    cudaGetSymbolAddress((void**)&option,   g_option);
    cudaGetSymbolAddress((void**)&logitD,   g_logitD);
    cudaGetSymbolAddress((void**)&kq,       g_kq);
    cudaGetSymbolAddress((void**)&attnD,    g_attnD);
    cudaGetSymbolAddress((void**)&cow,      g_cow);
    cudaGetSymbolAddress((void**)&coattn,   g_coattn);
    cudaGetSymbolAddress((void**)&fusion,   g_fusion);
    cudaGetSymbolAddress((void**)&logitS,   g_logitS);
    cudaGetSymbolAddress((void**)&attn2,    g_attn2);
    cudaGetSymbolAddress((void**)&fusion2,  g_fusion2);
    cudaGetSymbolAddress((void**)&rowq,     g_rowq);
    cudaGetSymbolAddress((void**)&rowk,     g_rowk);
    cudaGetSymbolAddress((void**)&rowkd,    g_rowkd);
    cudaGetSymbolAddress((void**)&opt_mask, g_opt_mask);
    cudaGetSymbolAddress((void**)&doc_mask, g_doc_mask);

    // fp16 weight slices inside g_Wh
    __half* Wcomp = Wh;                    // 7H*HD
    __half* Wgate = Wh + (size_t)7*HD*HD;  // 2H*HD
    __half* Wattn = Wh + (size_t)9*HD*HD;  // 3H*HD
    __half* Wself = Wh + (size_t)12*HD*HD; // 4H*HD

    const int EW_BLOCKS = (MR * HD) / 256;   // 65536
    const dim3 FC_GRID(HD/128, MR/128);      // 8 x 128

    // 0) convert FC weights to fp16 once (independent of everything else)
    k_cvtw<<<(7*HD*HD/4)/256, 256>>>(comp_fc_w, Wcomp);
    k_cvtw<<<(2*HD*HD/4)/256, 256>>>(gate_fc_w, Wgate);
    k_cvtw<<<(3*HD*HD/4)/256, 256>>>(attn_fc_w, Wattn);
    k_cvtw<<<(4*HD*HD/4)/256, 256>>>(self_fc_w, Wself);

    // 1) build encodings + masks
    k_build_opt<<<dim3(LO,  NRW), 256>>>(ll, am, fpw);
    k_build_doc<<<dim3(LDC, NRW), 256>>>(ll, am, fpw);

    // 2) opt-opt cross attention (192 pairs)
    k_rowdot<<<MR, 256>>>(opt_enc, opt_w1, rowq);
    k_rowdot<<<MR, 256>>>(opt_enc, opt_w2, rowk);
    k_gemm_nt<4><<<dim3(LO/128, LO/128, NPAIR), 256>>>(
        opt_enc, opt_enc, logitOpt, LO, LO, HD, 0,0,0,
        opt_w3, rowq, rowk, opt_mask, opt_mask, 0,0, 1);
    k_row_softmax<<<dim3(LO, NPAIR), 256>>>(logitOpt, LO, opt_mask, opt_mask, 0,0,0, 1);
    k_gemm_nn<<<dim3(HD/128, LO/128, NPAIR), 256>>>(
        logitOpt, opt_enc, attnOpt, LO, HD, LO, 0,0,0, 1);

    // 3) comp FC (K = 7H)
    k_feats<<<EW_BLOCKS, 256>>>();
    k_fc_mma<1><<<FC_GRID, 256>>>(Xh, Xl, Wcomp, corr, 7*HD, comp_fc_b, nullptr, nullptr);

    // 4) gate FC (K = 2H) with fused gate-combine -> option
    k_concat2<<<EW_BLOCKS, 256>>>();
    k_fc_mma<3><<<FC_GRID, 256>>>(Xh, Xl, Wgate, option, 2*HD, gate_fc_b, opt_enc, corr);

    // 5) doc attention (with co-attention)
    k_rowdot<<<MR, 256>>>(option, attn_w1, rowq);
    k_rowdot<<<NRW*LDC, 256>>>(doc_enc, attn_w2, rowkd);
    k_gemm_nt<4><<<dim3(LDC/128, LO/128, NRW), 256>>>(
        option, doc_enc, logitD, LO, LDC, HD,
        (long)LO*HD, (long)LDC*HD, (long)LO*LDC,
        attn_w3, rowq, rowkd, opt_mask, doc_mask, LO, LDC, 0);
    k_col_softmax<<<dim3(LDC/256, NRW), 256>>>();
    k_row_softmax<<<dim3(LO, NRW), 256>>>(logitD, LDC, opt_mask, doc_mask,
        (long)LO*LDC, LO, LDC, 0);
    k_gemm_nn<<<dim3(HD/128, LO/128, NRW), 256>>>(
        logitD, doc_enc, attnD, LO, HD, LDC,
        (long)LO*LDC, (long)LDC*HD, (long)LO*HD, 0);
    k_gemm_nt<0><<<dim3(LO/128, LO/128, NRW), 256>>>(
        logitD, kq, cow, LO, LO, LDC,
        (long)LO*LDC, (long)LO*LDC, (long)LO*LO,
        nullptr, nullptr, nullptr, nullptr, nullptr, 0,0, 0);
    k_gemm_nn<<<dim3(HD/128, LO/128, NRW), 256>>>(
        cow, option, coattn, LO, HD, LO,
        (long)LO*LO, (long)LO*HD, (long)LO*HD, 0);

    // 6) attn FC (K = 3H) -> fusion
    k_concat3<<<EW_BLOCKS, 256>>>();
    k_fc_mma<1><<<FC_GRID, 256>>>(Xh, Xl, Wattn, fusion, 3*HD, attn_fc_b, nullptr, nullptr);

    // 7) self attention
    k_rowdot<<<MR, 256>>>(fusion, self_w1, rowq);
    k_rowdot<<<MR, 256>>>(fusion, self_w2, rowk);
    k_gemm_nt<4><<<dim3(LO/128, LO/128, NRW), 256>>>(
        fusion, fusion, logitS, LO, LO, HD,
        (long)LO*HD, (long)LO*HD, (long)LO*LO,
        self_w3, rowq, rowk, opt_mask, opt_mask, LO, LO, 0);
    k_row_softmax<<<dim3(LO, NRW), 256>>>(logitS, LO, opt_mask, opt_mask,
        (long)LO*LO, LO, LO, 0);
    k_gemm_nn<<<dim3(HD/128, LO/128, NRW), 256>>>(
        logitS, fusion, attn2, LO, HD, LO,
        (long)LO*LO, (long)LO*HD, (long)LO*HD, 0);

    // 8) self FC (K = 4H) -> fusion2
    k_concat4<<<EW_BLOCKS, 256>>>();
    k_fc_mma<2><<<FC_GRID, 256>>>(Xh, Xl, Wself, fusion2, 4*HD, self_fc_b, nullptr, nullptr);

    // 9) masked max over option positions
    k_final<<<dim3(HD/256, NRW), 256>>>(out);
}